// round 4
// baseline (speedup 1.0000x reference)
#include <cuda_runtime.h>
#include <math.h>

typedef unsigned long long ull;
#define Tn 96
#define Bn 64
#define RS 66   // smem row stride in floats (8B aligned rows, mild 2-way conflicts)

__device__ __forceinline__ ull pk2(float lo, float hi) {
    ull r; asm("mov.b64 %0,{%1,%2};" : "=l"(r) : "f"(lo), "f"(hi)); return r;
}
__device__ __forceinline__ void upk2(ull v, float &a, float &b) {
    asm("mov.b64 {%0,%1},%2;" : "=f"(a), "=f"(b) : "l"(v));
}
__device__ __forceinline__ void ffma2(ull &d, ull a, ull b) {
    asm("fma.rn.f32x2 %0,%1,%2,%0;" : "+l"(d) : "l"(a), "l"(b));
}

// ---------- device-global scratch (no runtime allocation) ----------
__device__ __align__(256) float g_Pt[4 * 4096];                   // [m][k][n]
__device__ __align__(256) float g_WX[2][5 * 64 * 192];            // x-part weights [m][k][o]
__device__ __align__(256) float g_WgH[2][5 * 64 * 128];           // h-part gate weights [m][k][o]
__device__ __align__(256) float g_WcH[2][5 * 64 * 64];            // h-part cand weights [m][k][o]
__device__ __align__(256) float g_Gx[(size_t)Tn * Bn * 64 * 128]; // gate x-contribution (+bg)
__device__ __align__(256) float g_Cx[(size_t)Tn * Bn * 64 * 64];  // cand x-contribution (+bc)
__device__ __align__(256) float g_Hseq[(size_t)Tn * Bn * 4096];   // layer-0 outputs
__device__ __align__(256) float g_Last[Bn * 4096];

// ---------- P matrices: P1=S0, P2=2S0^2-I, P3=S1S0, P4=2S1P3-S0 ----------
__global__ void k_prep(const float* __restrict__ S0, const float* __restrict__ S1) {
    __shared__ float s0[4096], s1[4096];
    int tid = threadIdx.x;
    for (int i = tid; i < 4096; i += 256) { s0[i] = S0[i]; s1[i] = S1[i]; }
    __syncthreads();
    for (int i = tid; i < 4096; i += 256) {
        int n = i >> 6, k = i & 63;
        float a2 = 0.f, a3 = 0.f;
        for (int j = 0; j < 64; j++) {
            a2 += s0[n * 64 + j] * s0[j * 64 + k];
            a3 += s1[n * 64 + j] * s0[j * 64 + k];
        }
        g_Pt[k * 64 + n] = s0[i];
        g_Pt[4096 + k * 64 + n] = 2.f * a2 - (n == k ? 1.f : 0.f);
        g_Pt[2 * 4096 + k * 64 + n] = a3;
    }
    __syncthreads();
    for (int i = tid; i < 4096; i += 256) {
        int n = i >> 6, k = i & 63;
        float a4 = 0.f;
        for (int j = 0; j < 64; j++) a4 += s1[n * 64 + j] * g_Pt[2 * 4096 + k * 64 + j];
        g_Pt[3 * 4096 + k * 64 + n] = 2.f * a4 - s0[i];
    }
}

// ---------- weight repack: original row = f*5+m; f<64 x-part, f>=64 h-part ----------
__global__ void k_pack(const float* __restrict__ Wg0, const float* __restrict__ Wc0,
                       const float* __restrict__ Wg1, const float* __restrict__ Wc1) {
    const int WXsz = 5 * 64 * 192, WgHsz = 5 * 64 * 128, WcHsz = 5 * 64 * 64;
    const int PER_L = WXsz + WgHsz + WcHsz;
    for (int i = blockIdx.x * blockDim.x + threadIdx.x; i < 2 * PER_L; i += gridDim.x * blockDim.x) {
        int L = i / PER_L, r = i % PER_L;
        const float* Wg = L ? Wg1 : Wg0;
        const float* Wc = L ? Wc1 : Wc0;
        if (r < WXsz) {
            int m = r / (64 * 192), k = (r / 192) % 64, o = r % 192;
            g_WX[L][r] = (o < 128) ? Wg[(k * 5 + m) * 128 + o] : Wc[(k * 5 + m) * 64 + (o - 128)];
        } else if (r < WXsz + WgHsz) {
            int q = r - WXsz, m = q / (64 * 128), k = (q / 128) % 64, o = q % 128;
            g_WgH[L][q] = Wg[((64 + k) * 5 + m) * 128 + o];
        } else {
            int q = r - WXsz - WgHsz, m = q / 4096, k = (q / 64) % 64, o = q % 64;
            g_WcH[L][q] = Wc[((64 + k) * 5 + m) * 64 + o];
        }
    }
}

// ---------- parallel x-contribution precompute (per t,b) ----------
__global__ void k_pre(int layer, const float* __restrict__ xin,
                      const float* __restrict__ bg, const float* __restrict__ bc) {
    constexpr int OUT = 192, CPT = 24, NA = 12;
    extern __shared__ float sm[];
    float* hfull = sm;                // [64][RS]
    float* xsr = sm + 64 * RS;        // [128][RS]
    float* Bs = sm + 192 * RS;        // [64][192]
    const int tid = threadIdx.x;
    const int ng = blockIdx.x;
    const int t = blockIdx.y, b = blockIdx.z;

    const float* src = layer ? (g_Hseq + ((size_t)t * Bn + b) * 4096)
                             : (xin + ((size_t)b * Tn + t) * 4096);
    for (int i = tid * 2; i < 4096; i += 512) {
        int nn = i >> 6, c = i & 63;
        *(float2*)&hfull[nn * RS + c] = *(const float2*)&src[i];
    }
    __syncthreads();
    {
        int rowid = tid >> 1, jh = tid & 1;
        int m = rowid >> 5, nl = rowid & 31, nrow = ng * 32 + nl;
        ull acc[16];
#pragma unroll
        for (int j = 0; j < 16; j++) acc[j] = 0ull;
        const float* P = g_Pt + m * 4096 + nrow;
        for (int k = 0; k < 64; k++) {
            float p = __ldg(P + k * 64);
            ull p2 = pk2(p, p);
            const ull* xr = (const ull*)&hfull[k * RS + jh * 32];
#pragma unroll
            for (int j = 0; j < 16; j++) ffma2(acc[j], p2, xr[j]);
        }
        ull* dst = (ull*)&xsr[(m * 32 + nl) * RS + jh * 32];
#pragma unroll
        for (int j = 0; j < 16; j++) dst[j] = acc[j];
    }
    __syncthreads();

    const int nl = tid & 31, cg = tid >> 5;
    const int n = ng * 32 + nl;
    ull acc[NA];
#pragma unroll
    for (int j = 0; j < NA; j++) acc[j] = 0ull;
    const float* W = g_WX[layer];
    for (int m = 0; m < 5; m++) {
        const float4* s4 = (const float4*)(W + m * 64 * OUT);
        float4* d4 = (float4*)Bs;
        for (int i = tid; i < 64 * OUT / 4; i += 256) d4[i] = s4[i];
        __syncthreads();
        const float* A = (m == 0) ? &hfull[n * RS] : &xsr[((m - 1) * 32 + nl) * RS];
        for (int k = 0; k < 64; k++) {
            float a = A[k];
            ull a2 = pk2(a, a);
            const ull* br = (const ull*)&Bs[k * OUT + cg * CPT];
#pragma unroll
            for (int j = 0; j < NA; j++) ffma2(acc[j], a2, br[j]);
        }
        __syncthreads();
    }
    size_t gb = (((size_t)t * Bn + b) * 64 + n) * 128;
    size_t cb = (((size_t)t * Bn + b) * 64 + n) * 64;
#pragma unroll
    for (int j = 0; j < NA; j++) {
        int o = cg * CPT + 2 * j;
        float lo, hi; upk2(acc[j], lo, hi);
        if (o < 128) {
            g_Gx[gb + o] = lo + bg[o];
            g_Gx[gb + o + 1] = hi + bg[o + 1];
        } else {
            g_Cx[cb + o - 128] = lo + bc[o - 128];
            g_Cx[cb + o - 127] = hi + bc[o - 127];
        }
    }
}

// ---------- diffusion helper: src[64][RS] -> xs[4*64][RS] ----------
__device__ __forceinline__ void diffuse(const float* __restrict__ src, float* __restrict__ xs,
                                        const float* __restrict__ sP, int rowid, int jh,
                                        int dm, int dn) {
    ull acc[16];
#pragma unroll
    for (int j = 0; j < 16; j++) acc[j] = 0ull;
    const float* P = sP + dm * 4096 + dn;
    for (int k = 0; k < 64; k++) {
        float p = P[k * 64];
        ull p2 = pk2(p, p);
        const ull* xr = (const ull*)&src[k * RS + jh * 32];
#pragma unroll
        for (int j = 0; j < 16; j++) ffma2(acc[j], p2, xr[j]);
    }
    ull* dst = (ull*)&xs[rowid * RS + jh * 32];
#pragma unroll
    for (int j = 0; j < 16; j++) dst[j] = acc[j];
}

// ---------- persistent recurrence: one CTA per batch, all 96 steps in-kernel ----------
__global__ void __launch_bounds__(512, 1) k_recur(int layer, const int* __restrict__ seql) {
    extern __shared__ float sm[];
    float* sP  = sm;                   // 4*64*64 = 16384
    float* hs  = sP + 16384;           // 64*RS
    float* xs  = hs + 64 * RS;         // 256*RS
    float* rhs = xs + 256 * RS;        // 64*RS
    float* us  = rhs + 64 * RS;        // 64*RS
    float* Bs  = us + 64 * RS;         // 64*128 = 8192
    const int tid = threadIdx.x;
    const int b = blockIdx.x;

    for (int i = tid; i < 16384; i += 512) sP[i] = g_Pt[i];
    for (int i = tid; i < 64 * RS; i += 512) hs[i] = 0.f;
    __syncthreads();

    const int rowid = tid >> 1, jh = tid & 1;
    const int dm = rowid >> 6, dn = rowid & 63;
    const int n = tid & 63, cg = tid >> 6;
    const float4* Wg4 = (const float4*)g_WgH[layer];
    const float4* Wc4 = (const float4*)g_WcH[layer];
    const int last_t = seql[b] - 1;

    for (int t = 0; t < Tn; t++) {
        // ---- phase 1: diffusion of h -> xs
        diffuse(hs, xs, sP, rowid, jh, dm, dn);
        __syncthreads();

        // ---- phase 2: gate GEMM (128 cols; 16 cols/thread) with weight reg-prefetch
        {
            float4 pf[4];
#pragma unroll
            for (int j = 0; j < 4; j++) pf[j] = Wg4[tid + j * 512];
            ull acc[8];
#pragma unroll
            for (int j = 0; j < 8; j++) acc[j] = 0ull;
            for (int m = 0; m < 5; m++) {
#pragma unroll
                for (int j = 0; j < 4; j++) ((float4*)Bs)[tid + j * 512] = pf[j];
                __syncthreads();
                if (m < 4) {
#pragma unroll
                    for (int j = 0; j < 4; j++) pf[j] = Wg4[(m + 1) * 2048 + tid + j * 512];
                }
                const float* A = (m == 0) ? &hs[n * RS] : &xs[((m - 1) * 64 + n) * RS];
                for (int k = 0; k < 64; k++) {
                    float a = A[k];
                    ull a2 = pk2(a, a);
                    const ulonglong2* br = (const ulonglong2*)&Bs[k * 128 + cg * 16];
#pragma unroll
                    for (int j = 0; j < 4; j++) {
                        ulonglong2 w = br[j];
                        ffma2(acc[2 * j], a2, w.x);
                        ffma2(acc[2 * j + 1], a2, w.y);
                    }
                }
                __syncthreads();
            }
            const float* Gx = g_Gx + (((size_t)t * Bn + b) * 64 + n) * 128;
#pragma unroll
            for (int j = 0; j < 4; j++) {
#pragma unroll
                for (int s = 0; s < 2; s++) {
                    int o = cg * 16 + 4 * j + 2 * s;
                    float lo, hi; upk2(acc[2 * j + s], lo, hi);
                    float g0 = 1.f / (1.f + expf(-(lo + Gx[o])));
                    float g1 = 1.f / (1.f + expf(-(hi + Gx[o + 1])));
                    if (o < 64) {
                        rhs[n * RS + o] = g0 * hs[n * RS + o];
                        rhs[n * RS + o + 1] = g1 * hs[n * RS + o + 1];
                    } else {
                        us[n * RS + o - 64] = g0;
                        us[n * RS + o - 63] = g1;
                    }
                }
            }
        }
        __syncthreads();

        // ---- phase 3: diffusion of r*h -> xs
        diffuse(rhs, xs, sP, rowid, jh, dm, dn);
        __syncthreads();

        // ---- phase 4: cand GEMM (64 cols; 8 cols/thread) + GRU update
        {
            float4 pf[2];
#pragma unroll
            for (int j = 0; j < 2; j++) pf[j] = Wc4[tid + j * 512];
            ull acc[4];
#pragma unroll
            for (int j = 0; j < 4; j++) acc[j] = 0ull;
            for (int m = 0; m < 5; m++) {
#pragma unroll
                for (int j = 0; j < 2; j++) ((float4*)Bs)[tid + j * 512] = pf[j];
                __syncthreads();
                if (m < 4) {
#pragma unroll
                    for (int j = 0; j < 2; j++) pf[j] = Wc4[(m + 1) * 1024 + tid + j * 512];
                }
                const float* A = (m == 0) ? &rhs[n * RS] : &xs[((m - 1) * 64 + n) * RS];
                for (int k = 0; k < 64; k++) {
                    float a = A[k];
                    ull a2 = pk2(a, a);
                    const ulonglong2* br = (const ulonglong2*)&Bs[k * 64 + cg * 8];
#pragma unroll
                    for (int j = 0; j < 2; j++) {
                        ulonglong2 w = br[j];
                        ffma2(acc[2 * j], a2, w.x);
                        ffma2(acc[2 * j + 1], a2, w.y);
                    }
                }
                __syncthreads();
            }
            const float* Cx = g_Cx + (((size_t)t * Bn + b) * 64 + n) * 64;
            float* hseq = g_Hseq + ((size_t)t * Bn + b) * 4096 + n * 64;
            float* lastp = g_Last + (b * 64 + n) * 64;
            bool isLast = (layer == 1) && (t == last_t);
#pragma unroll
            for (int j = 0; j < 2; j++) {
#pragma unroll
                for (int s = 0; s < 2; s++) {
                    int o = cg * 8 + 4 * j + 2 * s;
                    float lo, hi; upk2(acc[2 * j + s], lo, hi);
                    float c0 = tanhf(lo + Cx[o]);
                    float c1 = tanhf(hi + Cx[o + 1]);
                    float u0 = us[n * RS + o], u1 = us[n * RS + o + 1];
                    float h0 = hs[n * RS + o], h1 = hs[n * RS + o + 1];
                    float n0 = u0 * h0 + (1.f - u0) * c0;
                    float n1 = u1 * h1 + (1.f - u1) * c1;
                    hs[n * RS + o] = n0;
                    hs[n * RS + o + 1] = n1;
                    if (layer == 0) { hseq[o] = n0; hseq[o + 1] = n1; }
                    if (isLast) { lastp[o] = n0; lastp[o + 1] = n1; }
                }
            }
        }
        __syncthreads();
    }
}

// ---------- output head ----------
__global__ void k_head(const float* __restrict__ fcw, const float* __restrict__ fcb,
                       const float* __restrict__ idw, const float* __restrict__ idb,
                       float* __restrict__ out) {
    __shared__ float hb[4096];
    __shared__ float w[64 * 54];
    __shared__ float bias[54];
    int b = blockIdx.x, tid = threadIdx.x;
    for (int i = tid; i < 4096; i += 256) hb[i] = fmaxf(g_Last[b * 4096 + i], 0.f);
    for (int i = tid; i < 64 * 54; i += 256) {
        int k = i / 54, c = i % 54;
        w[i] = (c < 4) ? fcw[k * 4 + c] : idw[k * 50 + c - 4];
    }
    if (tid < 54) bias[tid] = (tid < 4) ? fcb[tid] : idb[tid - 4];
    __syncthreads();
    if (tid < 54) {
        float best = -INFINITY;
        for (int nn = 0; nn < 64; nn++) {
            float s = bias[tid];
            for (int k = 0; k < 64; k++) s += hb[nn * 64 + k] * w[k * 54 + tid];
            best = fmaxf(best, s);
        }
        if (tid < 4) out[b * 4 + tid] = best;
        else out[256 + b * 50 + tid - 4] = best;
    }
}

extern "C" void kernel_launch(void* const* d_in, const int* in_sizes, int n_in,
                              void* d_out, int out_size) {
    const float* xseq = (const float*)d_in[0];
    const int* seql = (const int*)d_in[1];
    const float* S0 = (const float*)d_in[2];
    const float* S1 = (const float*)d_in[3];
    const float* Wg0 = (const float*)d_in[4]; const float* bg0 = (const float*)d_in[5];
    const float* Wc0 = (const float*)d_in[6]; const float* bc0 = (const float*)d_in[7];
    const float* Wg1 = (const float*)d_in[8]; const float* bg1 = (const float*)d_in[9];
    const float* Wc1 = (const float*)d_in[10]; const float* bc1 = (const float*)d_in[11];
    const float* fcw = (const float*)d_in[12]; const float* fcb = (const float*)d_in[13];
    const float* idw = (const float*)d_in[14]; const float* idb = (const float*)d_in[15];
    float* out = (float*)d_out;

    const int SM_PRE = 192 * RS * 4 + 64 * 192 * 4;                 // 99840
    const int SM_REC = (16384 + 64 * RS + 256 * RS + 64 * RS + 64 * RS + 8192) * 4; // 216576
    cudaFuncSetAttribute(k_pre, cudaFuncAttributeMaxDynamicSharedMemorySize, SM_PRE);
    cudaFuncSetAttribute(k_recur, cudaFuncAttributeMaxDynamicSharedMemorySize, SM_REC);

    k_prep<<<1, 256>>>(S0, S1);
    k_pack<<<240, 256>>>(Wg0, Wc0, Wg1, Wc1);

    k_pre<<<dim3(2, Tn, Bn), 256, SM_PRE>>>(0, xseq, bg0, bc0);
    k_recur<<<Bn, 512, SM_REC>>>(0, seql);
    k_pre<<<dim3(2, Tn, Bn), 256, SM_PRE>>>(1, xseq, bg1, bc1);
    k_recur<<<Bn, 512, SM_REC>>>(1, seql);

    k_head<<<Bn, 256>>>(fcw, fcb, idw, idb, out);
}

// round 5
// speedup vs baseline: 1.1534x; 1.1534x over previous
#include <cuda_runtime.h>
#include <math.h>

typedef unsigned long long ull;
#define Tn 96
#define Bn 64

__device__ __forceinline__ ull pk2(float lo, float hi) {
    ull r; asm("mov.b64 %0,{%1,%2};" : "=l"(r) : "f"(lo), "f"(hi)); return r;
}
__device__ __forceinline__ void upk2(ull v, float &a, float &b) {
    asm("mov.b64 {%0,%1},%2;" : "=f"(a), "=f"(b) : "l"(v));
}
__device__ __forceinline__ void ffma2(ull &d, ull a, ull b) {
    asm("fma.rn.f32x2 %0,%1,%2,%0;" : "+l"(d) : "l"(a), "l"(b));
}
__device__ __forceinline__ float sigm(float x) { return 1.f / (1.f + __expf(-x)); }
__device__ __forceinline__ float tanhfast(float x) {
    float t = __expf(-2.f * fabsf(x));
    float r = (1.f - t) / (1.f + t);
    return copysignf(r, x);
}

// ---------- device-global scratch ----------
__device__ __align__(256) float g_Pt[4 * 4096];                   // [m][k][n] = P_m[n][k]
__device__ __align__(256) float g_WX[2][5 * 64 * 192];
__device__ __align__(256) float g_WgH[2][5 * 64 * 128];
__device__ __align__(256) float g_WcH[2][5 * 64 * 64];
__device__ __align__(256) float g_Gx[(size_t)Tn * Bn * 64 * 128];
__device__ __align__(256) float g_Cx[(size_t)Tn * Bn * 64 * 64];
__device__ __align__(256) float g_Hseq[(size_t)Tn * Bn * 4096];
__device__ __align__(256) float g_Last[Bn * 4096];

// ---------- P matrices ----------
__global__ void k_prep(const float* __restrict__ S0, const float* __restrict__ S1) {
    __shared__ float s0[4096], s1[4096];
    int tid = threadIdx.x;
    for (int i = tid; i < 4096; i += 256) { s0[i] = S0[i]; s1[i] = S1[i]; }
    __syncthreads();
    for (int i = tid; i < 4096; i += 256) {
        int n = i >> 6, k = i & 63;
        float a2 = 0.f, a3 = 0.f;
        for (int j = 0; j < 64; j++) {
            a2 += s0[n * 64 + j] * s0[j * 64 + k];
            a3 += s1[n * 64 + j] * s0[j * 64 + k];
        }
        g_Pt[k * 64 + n] = s0[i];
        g_Pt[4096 + k * 64 + n] = 2.f * a2 - (n == k ? 1.f : 0.f);
        g_Pt[2 * 4096 + k * 64 + n] = a3;
    }
    __syncthreads();
    for (int i = tid; i < 4096; i += 256) {
        int n = i >> 6, k = i & 63;
        float a4 = 0.f;
        for (int j = 0; j < 64; j++) a4 += s1[n * 64 + j] * g_Pt[2 * 4096 + k * 64 + j];
        g_Pt[3 * 4096 + k * 64 + n] = 2.f * a4 - s0[i];
    }
}

// ---------- weight repack ----------
__global__ void k_pack(const float* __restrict__ Wg0, const float* __restrict__ Wc0,
                       const float* __restrict__ Wg1, const float* __restrict__ Wc1) {
    const int WXsz = 5 * 64 * 192, WgHsz = 5 * 64 * 128, WcHsz = 5 * 64 * 64;
    const int PER_L = WXsz + WgHsz + WcHsz;
    for (int i = blockIdx.x * blockDim.x + threadIdx.x; i < 2 * PER_L; i += gridDim.x * blockDim.x) {
        int L = i / PER_L, r = i % PER_L;
        const float* Wg = L ? Wg1 : Wg0;
        const float* Wc = L ? Wc1 : Wc0;
        if (r < WXsz) {
            int m = r / (64 * 192), k = (r / 192) % 64, o = r % 192;
            g_WX[L][r] = (o < 128) ? Wg[(k * 5 + m) * 128 + o] : Wc[(k * 5 + m) * 64 + (o - 128)];
        } else if (r < WXsz + WgHsz) {
            int q = r - WXsz, m = q / (64 * 128), k = (q / 128) % 64, o = q % 128;
            g_WgH[L][q] = Wg[((64 + k) * 5 + m) * 128 + o];
        } else {
            int q = r - WXsz - WgHsz, m = q / 4096, k = (q / 64) % 64, o = q % 64;
            g_WcH[L][q] = Wc[((64 + k) * 5 + m) * 64 + o];
        }
    }
}

// ---------- parallel x-contribution precompute (unchanged, known-good) ----------
#define RSP 66
__global__ void k_pre(int layer, const float* __restrict__ xin,
                      const float* __restrict__ bg, const float* __restrict__ bc) {
    constexpr int OUT = 192, CPT = 24, NA = 12;
    extern __shared__ float sm[];
    float* hfull = sm;
    float* xsr = sm + 64 * RSP;
    float* Bs = sm + 192 * RSP;
    const int tid = threadIdx.x;
    const int ng = blockIdx.x;
    const int t = blockIdx.y, b = blockIdx.z;

    const float* src = layer ? (g_Hseq + ((size_t)t * Bn + b) * 4096)
                             : (xin + ((size_t)b * Tn + t) * 4096);
    for (int i = tid * 2; i < 4096; i += 512) {
        int nn = i >> 6, c = i & 63;
        *(float2*)&hfull[nn * RSP + c] = *(const float2*)&src[i];
    }
    __syncthreads();
    {
        int rowid = tid >> 1, jh = tid & 1;
        int m = rowid >> 5, nl = rowid & 31, nrow = ng * 32 + nl;
        ull acc[16];
#pragma unroll
        for (int j = 0; j < 16; j++) acc[j] = 0ull;
        const float* P = g_Pt + m * 4096 + nrow;
        for (int k = 0; k < 64; k++) {
            float p = __ldg(P + k * 64);
            ull p2 = pk2(p, p);
            const ull* xr = (const ull*)&hfull[k * RSP + jh * 32];
#pragma unroll
            for (int j = 0; j < 16; j++) ffma2(acc[j], p2, xr[j]);
        }
        ull* dst = (ull*)&xsr[(m * 32 + nl) * RSP + jh * 32];
#pragma unroll
        for (int j = 0; j < 16; j++) dst[j] = acc[j];
    }
    __syncthreads();

    const int nl = tid & 31, cg = tid >> 5;
    const int n = ng * 32 + nl;
    ull acc[NA];
#pragma unroll
    for (int j = 0; j < NA; j++) acc[j] = 0ull;
    const float* W = g_WX[layer];
    for (int m = 0; m < 5; m++) {
        const float4* s4 = (const float4*)(W + m * 64 * OUT);
        float4* d4 = (float4*)Bs;
        for (int i = tid; i < 64 * OUT / 4; i += 256) d4[i] = s4[i];
        __syncthreads();
        const float* A = (m == 0) ? &hfull[n * RSP] : &xsr[((m - 1) * 32 + nl) * RSP];
        for (int k = 0; k < 64; k++) {
            float a = A[k];
            ull a2 = pk2(a, a);
            const ull* br = (const ull*)&Bs[k * OUT + cg * CPT];
#pragma unroll
            for (int j = 0; j < NA; j++) ffma2(acc[j], a2, br[j]);
        }
        __syncthreads();
    }
    size_t gb = (((size_t)t * Bn + b) * 64 + n) * 128;
    size_t cb = (((size_t)t * Bn + b) * 64 + n) * 64;
#pragma unroll
    for (int j = 0; j < NA; j++) {
        int o = cg * CPT + 2 * j;
        float lo, hi; upk2(acc[j], lo, hi);
        if (o < 128) {
            g_Gx[gb + o] = lo + bg[o];
            g_Gx[gb + o + 1] = hi + bg[o + 1];
        } else {
            g_Cx[cb + o - 128] = lo + bc[o - 128];
            g_Cx[cb + o - 127] = hi + bc[o - 127];
        }
    }
}

// ---------- diffusion slice: xb[f][n] = sum_k PT[k][n] * srcN[k][f] ----------
__device__ __forceinline__ void diffuse_slice(const float* __restrict__ srcN,
                                              const float* __restrict__ P,
                                              float* __restrict__ xb, int n, int fg) {
    ull d0 = 0, d1 = 0, d2 = 0, d3 = 0;
    const float* hrow = srcN + fg * 8;
    for (int k = 0; k < 64; k++) {
        float p = P[k * 64 + n];
        ull p2 = pk2(p, p);
        const ulonglong2* hv = (const ulonglong2*)(hrow + k * 68);
        ulonglong2 v0 = hv[0], v1 = hv[1];
        ffma2(d0, p2, v0.x); ffma2(d1, p2, v0.y);
        ffma2(d2, p2, v1.x); ffma2(d3, p2, v1.y);
    }
    float a, bb;
    upk2(d0, a, bb); xb[(fg * 8 + 0) * 66 + n] = a; xb[(fg * 8 + 1) * 66 + n] = bb;
    upk2(d1, a, bb); xb[(fg * 8 + 2) * 66 + n] = a; xb[(fg * 8 + 3) * 66 + n] = bb;
    upk2(d2, a, bb); xb[(fg * 8 + 4) * 66 + n] = a; xb[(fg * 8 + 5) * 66 + n] = bb;
    upk2(d3, a, bb); xb[(fg * 8 + 6) * 66 + n] = a; xb[(fg * 8 + 7) * 66 + n] = bb;
}

// ---------- persistent recurrence v2: transposed layouts, crossbar-lean ----------
__global__ void __launch_bounds__(512, 1) k_recur(int layer, const int* __restrict__ seql) {
    extern __shared__ float sm[];
    float* sPT = sm;                 // [4][64k][64n]           16384
    float* hT  = sm + 16384;         // [64f][66]  h transposed
    float* hN  = hT + 64 * 66;       // [64n][68]  h node-major
    float* rhT = hN + 64 * 68;       // [64f][66]
    float* rhN = rhT + 64 * 66;      // [64n][68]
    float* uN  = rhN + 64 * 68;      // [64n][68]
    float* xb  = uN + 64 * 68;       // [64f][66] one diffusion slice
    float* Bs  = xb + 64 * 66;       // [64][128] weight tile

    const int tid = threadIdx.x;
    const int b = blockIdx.x;
    const int n = tid & 63;
    const int cg = tid >> 6;   // 0..7

    for (int i = tid; i < 16384; i += 512) sPT[i] = g_Pt[i];
    for (int i = tid; i < 64 * 66; i += 512) hT[i] = 0.f;
    for (int i = tid; i < 64 * 68; i += 512) hN[i] = 0.f;
    __syncthreads();

    const float4* Wg4 = (const float4*)g_WgH[layer];
    const float4* Wc4 = (const float4*)g_WcH[layer];
    const int last_t = seql[b] - 1;

    for (int t = 0; t < Tn; t++) {
        // ============ GATE: 128 cols, 16/thread ============
        {
            const float* GxP = g_Gx + (((size_t)t * Bn + b) * 64 + n) * 128 + cg * 16;
            float gxv[16];
#pragma unroll
            for (int j = 0; j < 4; j++) {
                float4 v = __ldg((const float4*)GxP + j);
                gxv[4 * j] = v.x; gxv[4 * j + 1] = v.y; gxv[4 * j + 2] = v.z; gxv[4 * j + 3] = v.w;
            }
            ull acc[8];
#pragma unroll
            for (int j = 0; j < 8; j++) acc[j] = 0ull;
            float4 pf0 = Wg4[tid], pf1 = Wg4[tid + 512], pf2 = Wg4[tid + 1024], pf3 = Wg4[tid + 1536];
            for (int m = 0; m < 5; m++) {
                ((float4*)Bs)[tid] = pf0; ((float4*)Bs)[tid + 512] = pf1;
                ((float4*)Bs)[tid + 1024] = pf2; ((float4*)Bs)[tid + 1536] = pf3;
                if (m < 4) {
                    pf0 = Wg4[(m + 1) * 2048 + tid];       pf1 = Wg4[(m + 1) * 2048 + tid + 512];
                    pf2 = Wg4[(m + 1) * 2048 + tid + 1024]; pf3 = Wg4[(m + 1) * 2048 + tid + 1536];
                }
                if (m >= 1) diffuse_slice(hN, sPT + (m - 1) * 4096, xb, n, cg);
                __syncthreads();
                const float* A = (m == 0) ? hT : xb;
                for (int k = 0; k < 64; k++) {
                    float a = A[k * 66 + n];
                    ull a2 = pk2(a, a);
                    const ulonglong2* br = (const ulonglong2*)(Bs + k * 128 + cg * 16);
                    ulonglong2 w0 = br[0], w1 = br[1], w2 = br[2], w3 = br[3];
                    ffma2(acc[0], a2, w0.x); ffma2(acc[1], a2, w0.y);
                    ffma2(acc[2], a2, w1.x); ffma2(acc[3], a2, w1.y);
                    ffma2(acc[4], a2, w2.x); ffma2(acc[5], a2, w2.y);
                    ffma2(acc[6], a2, w3.x); ffma2(acc[7], a2, w3.y);
                }
                __syncthreads();
            }
            // epilogue
#pragma unroll
            for (int j = 0; j < 8; j++) {
                int o = cg * 16 + 2 * j;
                float lo, hi; upk2(acc[j], lo, hi);
                float s0 = sigm(lo + gxv[2 * j]);
                float s1 = sigm(hi + gxv[2 * j + 1]);
                if (cg < 4) {
                    float h0 = hN[n * 68 + o], h1 = hN[n * 68 + o + 1];
                    float r0 = s0 * h0, r1 = s1 * h1;
                    rhT[o * 66 + n] = r0; rhT[(o + 1) * 66 + n] = r1;
                    rhN[n * 68 + o] = r0; rhN[n * 68 + o + 1] = r1;
                } else {
                    uN[n * 68 + (o - 64)] = s0; uN[n * 68 + (o - 63)] = s1;
                }
            }
        }
        __syncthreads();

        // ============ CAND: 64 cols, 8/thread ============
        {
            const float* CxP = g_Cx + (((size_t)t * Bn + b) * 64 + n) * 64 + cg * 8;
            float cxv[8];
#pragma unroll
            for (int j = 0; j < 2; j++) {
                float4 v = __ldg((const float4*)CxP + j);
                cxv[4 * j] = v.x; cxv[4 * j + 1] = v.y; cxv[4 * j + 2] = v.z; cxv[4 * j + 3] = v.w;
            }
            ull acc[4];
#pragma unroll
            for (int j = 0; j < 4; j++) acc[j] = 0ull;
            float4 pf0 = Wc4[tid], pf1 = Wc4[tid + 512];
            for (int m = 0; m < 5; m++) {
                ((float4*)Bs)[tid] = pf0; ((float4*)Bs)[tid + 512] = pf1;
                if (m < 4) {
                    pf0 = Wc4[(m + 1) * 1024 + tid];
                    pf1 = Wc4[(m + 1) * 1024 + tid + 512];
                }
                if (m >= 1) diffuse_slice(rhN, sPT + (m - 1) * 4096, xb, n, cg);
                __syncthreads();
                const float* A = (m == 0) ? rhT : xb;
                for (int k = 0; k < 64; k++) {
                    float a = A[k * 66 + n];
                    ull a2 = pk2(a, a);
                    const ulonglong2* br = (const ulonglong2*)(Bs + k * 64 + cg * 8);
                    ulonglong2 w0 = br[0];
                    ffma2(acc[0], a2, w0.x); ffma2(acc[1], a2, w0.y);
                    ulonglong2 w1 = br[1];
                    ffma2(acc[2], a2, w1.x); ffma2(acc[3], a2, w1.y);
                }
                __syncthreads();
            }
            // epilogue: GRU update
            float* hseq = g_Hseq + ((size_t)t * Bn + b) * 4096 + n * 64;
            float* lastp = g_Last + (b * 64 + n) * 64;
            bool isLast = (layer == 1) && (t == last_t);
#pragma unroll
            for (int j = 0; j < 4; j++) {
                int o = cg * 8 + 2 * j;
                float lo, hi; upk2(acc[j], lo, hi);
                float c0 = tanhfast(lo + cxv[2 * j]);
                float c1 = tanhfast(hi + cxv[2 * j + 1]);
                float u0 = uN[n * 68 + o], u1 = uN[n * 68 + o + 1];
                float h0 = hN[n * 68 + o], h1 = hN[n * 68 + o + 1];
                float n0 = u0 * h0 + (1.f - u0) * c0;
                float n1 = u1 * h1 + (1.f - u1) * c1;
                hN[n * 68 + o] = n0; hN[n * 68 + o + 1] = n1;
                hT[o * 66 + n] = n0; hT[(o + 1) * 66 + n] = n1;
                if (layer == 0) { hseq[o] = n0; hseq[o + 1] = n1; }
                if (isLast) { lastp[o] = n0; lastp[o + 1] = n1; }
            }
        }
        __syncthreads();
    }
}

// ---------- output head ----------
__global__ void k_head(const float* __restrict__ fcw, const float* __restrict__ fcb,
                       const float* __restrict__ idw, const float* __restrict__ idb,
                       float* __restrict__ out) {
    __shared__ float hb[4096];
    __shared__ float w[64 * 54];
    __shared__ float bias[54];
    int b = blockIdx.x, tid = threadIdx.x;
    for (int i = tid; i < 4096; i += 256) hb[i] = fmaxf(g_Last[b * 4096 + i], 0.f);
    for (int i = tid; i < 64 * 54; i += 256) {
        int k = i / 54, c = i % 54;
        w[i] = (c < 4) ? fcw[k * 4 + c] : idw[k * 50 + c - 4];
    }
    if (tid < 54) bias[tid] = (tid < 4) ? fcb[tid] : idb[tid - 4];
    __syncthreads();
    if (tid < 54) {
        float best = -INFINITY;
        for (int nn = 0; nn < 64; nn++) {
            float s = bias[tid];
            for (int k = 0; k < 64; k++) s += hb[nn * 64 + k] * w[k * 54 + tid];
            best = fmaxf(best, s);
        }
        if (tid < 4) out[b * 4 + tid] = best;
        else out[256 + b * 50 + tid - 4] = best;
    }
}

extern "C" void kernel_launch(void* const* d_in, const int* in_sizes, int n_in,
                              void* d_out, int out_size) {
    const float* xseq = (const float*)d_in[0];
    const int* seql = (const int*)d_in[1];
    const float* S0 = (const float*)d_in[2];
    const float* S1 = (const float*)d_in[3];
    const float* Wg0 = (const float*)d_in[4]; const float* bg0 = (const float*)d_in[5];
    const float* Wc0 = (const float*)d_in[6]; const float* bc0 = (const float*)d_in[7];
    const float* Wg1 = (const float*)d_in[8]; const float* bg1 = (const float*)d_in[9];
    const float* Wc1 = (const float*)d_in[10]; const float* bc1 = (const float*)d_in[11];
    const float* fcw = (const float*)d_in[12]; const float* fcb = (const float*)d_in[13];
    const float* idw = (const float*)d_in[14]; const float* idb = (const float*)d_in[15];
    float* out = (float*)d_out;

    const int SM_PRE = 192 * RSP * 4 + 64 * 192 * 4;   // 99840
    const int SM_REC = (16384 + 64*66 + 64*68 + 64*66 + 64*68 + 64*68 + 64*66 + 64*128) * 4; // 201216
    cudaFuncSetAttribute(k_pre, cudaFuncAttributeMaxDynamicSharedMemorySize, SM_PRE);
    cudaFuncSetAttribute(k_recur, cudaFuncAttributeMaxDynamicSharedMemorySize, SM_REC);

    k_prep<<<1, 256>>>(S0, S1);
    k_pack<<<240, 256>>>(Wg0, Wc0, Wg1, Wc1);

    k_pre<<<dim3(2, Tn, Bn), 256, SM_PRE>>>(0, xseq, bg0, bc0);
    k_recur<<<Bn, 512, SM_REC>>>(0, seql);
    k_pre<<<dim3(2, Tn, Bn), 256, SM_PRE>>>(1, xseq, bg1, bc1);
    k_recur<<<Bn, 512, SM_REC>>>(1, seql);

    k_head<<<Bn, 256>>>(fcw, fcb, idw, idb, out);
}

// round 6
// speedup vs baseline: 1.5441x; 1.3387x over previous
#include <cuda_runtime.h>
#include <math.h>

typedef unsigned long long ull;
#define Tn 96
#define Bn 64

__device__ __forceinline__ ull pk2(float lo, float hi) {
    ull r; asm("mov.b64 %0,{%1,%2};" : "=l"(r) : "f"(lo), "f"(hi)); return r;
}
__device__ __forceinline__ void upk2(ull v, float &a, float &b) {
    asm("mov.b64 {%0,%1},%2;" : "=f"(a), "=f"(b) : "l"(v));
}
__device__ __forceinline__ void ffma2(ull &d, ull a, ull b) {
    asm("fma.rn.f32x2 %0,%1,%2,%0;" : "+l"(d) : "l"(a), "l"(b));
}
__device__ __forceinline__ float sigm(float x) { return 1.f / (1.f + __expf(-x)); }
__device__ __forceinline__ float tanhfast(float x) {
    float t = __expf(-2.f * fabsf(x));
    return copysignf((1.f - t) / (1.f + t), x);
}
__device__ __forceinline__ void flag_release(int* p) {
    asm volatile("red.release.gpu.global.add.s32 [%0], 1;" :: "l"(p) : "memory");
}
__device__ __forceinline__ int flag_acq(const int* p) {
    int v; asm volatile("ld.acquire.gpu.global.s32 %0, [%1];" : "=r"(v) : "l"(p) : "memory");
    return v;
}

// ---------- device-global scratch ----------
__device__ __align__(256) float g_Pt[4 * 4096];                   // [m][k][n] = P_m[n][k]
__device__ __align__(256) float g_WX[2][5 * 64 * 192];
__device__ __align__(256) float g_WgH[2][5 * 64 * 128];
__device__ __align__(256) float g_WcH[2][5 * 64 * 64];
__device__ __align__(256) float g_Gx[(size_t)Tn * Bn * 64 * 128];
__device__ __align__(256) float g_Cx[(size_t)Tn * Bn * 64 * 64];
__device__ __align__(256) float g_Hseq[(size_t)Tn * Bn * 4096];
__device__ __align__(256) float g_Last[Bn * 4096];
__device__ __align__(256) float g_xRH[128 * 2048];                // per-CTA rh half exchange
__device__ __align__(256) float g_xH[128 * 2048];                 // per-CTA h half exchange
__device__ __align__(256) int   g_flag[2][2][2][64];              // [layer][phase][hf][b]

// ---------- P matrices: P1=S0, P2=2S0^2-I, P3=S1S0, P4=2S1P3-S0 ----------
__global__ void k_prep(const float* __restrict__ S0, const float* __restrict__ S1) {
    __shared__ float s0[4096], s1[4096];
    int tid = threadIdx.x;
    for (int i = tid; i < 512; i += 256) ((int*)g_flag)[i] = 0;   // reset sync flags each replay
    for (int i = tid; i < 4096; i += 256) { s0[i] = S0[i]; s1[i] = S1[i]; }
    __syncthreads();
    for (int i = tid; i < 4096; i += 256) {
        int n = i >> 6, k = i & 63;
        float a2 = 0.f, a3 = 0.f;
        for (int j = 0; j < 64; j++) {
            a2 += s0[n * 64 + j] * s0[j * 64 + k];
            a3 += s1[n * 64 + j] * s0[j * 64 + k];
        }
        g_Pt[k * 64 + n] = s0[i];
        g_Pt[4096 + k * 64 + n] = 2.f * a2 - (n == k ? 1.f : 0.f);
        g_Pt[2 * 4096 + k * 64 + n] = a3;
    }
    __syncthreads();
    for (int i = tid; i < 4096; i += 256) {
        int n = i >> 6, k = i & 63;
        float a4 = 0.f;
        for (int j = 0; j < 64; j++) a4 += s1[n * 64 + j] * g_Pt[2 * 4096 + k * 64 + j];
        g_Pt[3 * 4096 + k * 64 + n] = 2.f * a4 - s0[i];
    }
}

// ---------- weight repack ----------
__global__ void k_pack(const float* __restrict__ Wg0, const float* __restrict__ Wc0,
                       const float* __restrict__ Wg1, const float* __restrict__ Wc1) {
    const int WXsz = 5 * 64 * 192, WgHsz = 5 * 64 * 128, WcHsz = 5 * 64 * 64;
    const int PER_L = WXsz + WgHsz + WcHsz;
    for (int i = blockIdx.x * blockDim.x + threadIdx.x; i < 2 * PER_L; i += gridDim.x * blockDim.x) {
        int L = i / PER_L, r = i % PER_L;
        const float* Wg = L ? Wg1 : Wg0;
        const float* Wc = L ? Wc1 : Wc0;
        if (r < WXsz) {
            int m = r / (64 * 192), k = (r / 192) % 64, o = r % 192;
            g_WX[L][r] = (o < 128) ? Wg[(k * 5 + m) * 128 + o] : Wc[(k * 5 + m) * 64 + (o - 128)];
        } else if (r < WXsz + WgHsz) {
            int q = r - WXsz, m = q / (64 * 128), k = (q / 128) % 64, o = q % 128;
            g_WgH[L][q] = Wg[((64 + k) * 5 + m) * 128 + o];
        } else {
            int q = r - WXsz - WgHsz, m = q / 4096, k = (q / 64) % 64, o = q % 64;
            g_WcH[L][q] = Wc[((64 + k) * 5 + m) * 64 + o];
        }
    }
}

// ---------- parallel x-contribution precompute ----------
#define RSP 66
__global__ void k_pre(int layer, const float* __restrict__ xin,
                      const float* __restrict__ bg, const float* __restrict__ bc) {
    constexpr int OUT = 192, CPT = 24, NA = 12;
    extern __shared__ float sm[];
    float* hfull = sm;
    float* xsr = sm + 64 * RSP;
    float* Bs = sm + 192 * RSP;
    const int tid = threadIdx.x;
    const int ng = blockIdx.x;
    const int t = blockIdx.y, b = blockIdx.z;

    const float* src = layer ? (g_Hseq + ((size_t)t * Bn + b) * 4096)
                             : (xin + ((size_t)b * Tn + t) * 4096);
    for (int i = tid * 2; i < 4096; i += 512) {
        int nn = i >> 6, c = i & 63;
        *(float2*)&hfull[nn * RSP + c] = *(const float2*)&src[i];
    }
    __syncthreads();
    {
        int rowid = tid >> 1, jh = tid & 1;
        int m = rowid >> 5, nl = rowid & 31, nrow = ng * 32 + nl;
        ull acc[16];
#pragma unroll
        for (int j = 0; j < 16; j++) acc[j] = 0ull;
        const float* P = g_Pt + m * 4096 + nrow;
        for (int k = 0; k < 64; k++) {
            float p = __ldg(P + k * 64);
            ull p2 = pk2(p, p);
            const ull* xr = (const ull*)&hfull[k * RSP + jh * 32];
#pragma unroll
            for (int j = 0; j < 16; j++) ffma2(acc[j], p2, xr[j]);
        }
        ull* dst = (ull*)&xsr[(m * 32 + nl) * RSP + jh * 32];
#pragma unroll
        for (int j = 0; j < 16; j++) dst[j] = acc[j];
    }
    __syncthreads();

    const int nl = tid & 31, cg = tid >> 5;
    const int n = ng * 32 + nl;
    ull acc[NA];
#pragma unroll
    for (int j = 0; j < NA; j++) acc[j] = 0ull;
    const float* W = g_WX[layer];
    for (int m = 0; m < 5; m++) {
        const float4* s4 = (const float4*)(W + m * 64 * OUT);
        float4* d4 = (float4*)Bs;
        for (int i = tid; i < 64 * OUT / 4; i += 256) d4[i] = s4[i];
        __syncthreads();
        const float* A = (m == 0) ? &hfull[n * RSP] : &xsr[((m - 1) * 32 + nl) * RSP];
        for (int k = 0; k < 64; k++) {
            float a = A[k];
            ull a2 = pk2(a, a);
            const ulonglong2* br = (const ulonglong2*)&Bs[k * OUT + cg * CPT];
#pragma unroll
            for (int j = 0; j < NA / 2; j++) {
                ulonglong2 w = br[j];
                ffma2(acc[2 * j], a2, w.x);
                ffma2(acc[2 * j + 1], a2, w.y);
            }
        }
        __syncthreads();
    }
    size_t gb = (((size_t)t * Bn + b) * 64 + n) * 128;
    size_t cb = (((size_t)t * Bn + b) * 64 + n) * 64;
#pragma unroll
    for (int j = 0; j < NA; j++) {
        int o = cg * CPT + 2 * j;
        float lo, hi; upk2(acc[j], lo, hi);
        if (o < 128) {
            g_Gx[gb + o] = lo + bg[o];
            g_Gx[gb + o + 1] = hi + bg[o + 1];
        } else {
            g_Cx[cb + o - 128] = lo + bc[o - 128];
            g_Cx[cb + o - 127] = hi + bc[o - 127];
        }
    }
}

// ---------- half-node diffusion: xb[f][nl] = sum_k P_m[hf*32+nl][k] * srcN[k][f] ----------
__device__ __forceinline__ void diffuse_half(const float* __restrict__ srcN,
                                             const float* __restrict__ sPh_m,
                                             float* __restrict__ xb, int nl, int fg) {
    ull d0 = 0, d1 = 0;
    const float* P = sPh_m + nl;
    for (int k = 0; k < 64; k++) {
        float p = P[k * 32];
        ull p2 = pk2(p, p);
        ulonglong2 v = *(const ulonglong2*)(srcN + k * 68 + fg * 4);
        ffma2(d0, p2, v.x);
        ffma2(d1, p2, v.y);
    }
    float a, b;
    upk2(d0, a, b); xb[(fg * 4 + 0) * 34 + nl] = a; xb[(fg * 4 + 1) * 34 + nl] = b;
    upk2(d1, a, b); xb[(fg * 4 + 2) * 34 + nl] = a; xb[(fg * 4 + 3) * 34 + nl] = b;
}

// ---------- persistent recurrence v3: 2 CTAs per batch (node halves), gmem flag sync ----------
__global__ void __launch_bounds__(512, 1) k_recur(int layer, const int* __restrict__ seql) {
    extern __shared__ float sm[];
    float* Bs  = sm;                  // [64][128]          8192 f
    float* hN  = Bs + 8192;           // [64][68] full      4352 f
    float* rhN = hN + 64 * 68;        // [64][68] full      4352 f
    float* sPh = rhN + 64 * 68;       // [4][64][32]        8192 f
    float* hT  = sPh + 8192;          // [64f][34] own half 2176 f
    float* rhT = hT + 64 * 34;        // [64f][34]          2176 f
    float* uH  = rhT + 64 * 34;       // [32][68]           2176 f
    float* xb  = uH + 32 * 68;        // [64f][34]          2176 f

    const int tid = threadIdx.x;
    const int hf = blockIdx.x;        // node half 0/1
    const int b = blockIdx.y;
    const int nl = tid & 31;
    const int cg = tid >> 5;          // 0..15
    const int ng = hf * 32 + nl;      // global node for this thread's GEMM row
    const int peer = b * 2 + (hf ^ 1);
    const int self = b * 2 + hf;

    for (int i = tid; i < 8192; i += 512) {
        int m = i >> 11, r = i & 2047, k = r >> 5, nn = r & 31;
        sPh[i] = g_Pt[m * 4096 + k * 64 + hf * 32 + nn];
    }
    for (int i = tid; i < 64 * 68; i += 512) hN[i] = 0.f;
    for (int i = tid; i < 64 * 34; i += 512) hT[i] = 0.f;
    __syncthreads();

    const float4* Wg4 = (const float4*)g_WgH[layer];
    const float4* Wc4 = (const float4*)g_WcH[layer];
    int* fRH_self = &g_flag[layer][0][hf][b];
    int* fRH_peer = &g_flag[layer][0][hf ^ 1][b];
    int* fH_self  = &g_flag[layer][1][hf][b];
    int* fH_peer  = &g_flag[layer][1][hf ^ 1][b];
    const int last_t = seql[b] - 1;

    for (int t = 0; t < Tn; t++) {
        // ================= GATE =================
        {
            const float* GxP = g_Gx + (((size_t)t * Bn + b) * 64 + ng) * 128 + cg * 8;
            float4 gx0 = __ldg((const float4*)GxP);
            float4 gx1 = __ldg((const float4*)GxP + 1);
            ull acc[4];
#pragma unroll
            for (int j = 0; j < 4; j++) acc[j] = 0ull;
            float4 pf0 = Wg4[tid], pf1 = Wg4[tid + 512], pf2 = Wg4[tid + 1024], pf3 = Wg4[tid + 1536];
            for (int m = 0; m < 5; m++) {
                ((float4*)Bs)[tid] = pf0; ((float4*)Bs)[tid + 512] = pf1;
                ((float4*)Bs)[tid + 1024] = pf2; ((float4*)Bs)[tid + 1536] = pf3;
                if (m < 4) {
                    pf0 = Wg4[(m + 1) * 2048 + tid];        pf1 = Wg4[(m + 1) * 2048 + tid + 512];
                    pf2 = Wg4[(m + 1) * 2048 + tid + 1024]; pf3 = Wg4[(m + 1) * 2048 + tid + 1536];
                }
                if (m >= 1) diffuse_half(hN, sPh + (m - 1) * 2048, xb, nl, cg);
                __syncthreads();
                const float* A = (m == 0) ? (hT + nl) : (xb + nl);
                for (int k = 0; k < 64; k++) {
                    float a = A[k * 34];
                    ull a2 = pk2(a, a);
                    const ulonglong2* br = (const ulonglong2*)(Bs + k * 128 + cg * 8);
                    ulonglong2 w0 = br[0], w1 = br[1];
                    ffma2(acc[0], a2, w0.x); ffma2(acc[1], a2, w0.y);
                    ffma2(acc[2], a2, w1.x); ffma2(acc[3], a2, w1.y);
                }
                __syncthreads();
            }
            float gx[8] = {gx0.x, gx0.y, gx0.z, gx0.w, gx1.x, gx1.y, gx1.z, gx1.w};
            if (cg < 8) {
                float rv[8];
#pragma unroll
                for (int j = 0; j < 4; j++) {
                    int o = cg * 8 + 2 * j;
                    float lo, hi; upk2(acc[j], lo, hi);
                    float r0 = sigm(lo + gx[2 * j]) * hN[ng * 68 + o];
                    float r1 = sigm(hi + gx[2 * j + 1]) * hN[ng * 68 + o + 1];
                    rhN[ng * 68 + o] = r0; rhN[ng * 68 + o + 1] = r1;
                    rhT[o * 34 + nl] = r0; rhT[(o + 1) * 34 + nl] = r1;
                    rv[2 * j] = r0; rv[2 * j + 1] = r1;
                }
                float4* dst = (float4*)(g_xRH + (size_t)self * 2048 + nl * 64 + cg * 8);
                __stcg(dst, make_float4(rv[0], rv[1], rv[2], rv[3]));
                __stcg(dst + 1, make_float4(rv[4], rv[5], rv[6], rv[7]));
            } else {
#pragma unroll
                for (int j = 0; j < 4; j++) {
                    int o = cg * 8 + 2 * j;
                    float lo, hi; upk2(acc[j], lo, hi);
                    uH[nl * 68 + (o - 64)] = sigm(lo + gx[2 * j]);
                    uH[nl * 68 + (o - 63)] = sigm(hi + gx[2 * j + 1]);
                }
            }
        }
        __syncthreads();
        if (tid == 0) {
            flag_release(fRH_self);
            while (flag_acq(fRH_peer) < t + 1) { }
        }
        __syncthreads();
        {   // import peer rh half
            float4 v = __ldcg((const float4*)(g_xRH + (size_t)peer * 2048) + tid);
            int row = tid >> 4, col = (tid * 4) & 63;
            int pn = (hf ^ 1) * 32 + row;
            *(float4*)&rhN[pn * 68 + col] = v;
        }
        __syncthreads();

        // ================= CAND =================
        {
            const float* CxP = g_Cx + (((size_t)t * Bn + b) * 64 + ng) * 64 + cg * 4;
            float4 cx = __ldg((const float4*)CxP);
            ull acc[2]; acc[0] = 0ull; acc[1] = 0ull;
            float4 pf0 = Wc4[tid], pf1 = Wc4[tid + 512];
            for (int m = 0; m < 5; m++) {
                ((float4*)Bs)[tid] = pf0; ((float4*)Bs)[tid + 512] = pf1;
                if (m < 4) {
                    pf0 = Wc4[(m + 1) * 1024 + tid];
                    pf1 = Wc4[(m + 1) * 1024 + tid + 512];
                }
                if (m >= 1) diffuse_half(rhN, sPh + (m - 1) * 2048, xb, nl, cg);
                __syncthreads();
                const float* A = (m == 0) ? (rhT + nl) : (xb + nl);
                for (int k = 0; k < 64; k++) {
                    float a = A[k * 34];
                    ull a2 = pk2(a, a);
                    ulonglong2 w = *(const ulonglong2*)(Bs + k * 64 + cg * 4);
                    ffma2(acc[0], a2, w.x);
                    ffma2(acc[1], a2, w.y);
                }
                __syncthreads();
            }
            float cxv[4] = {cx.x, cx.y, cx.z, cx.w};
            float hv[4];
            bool isLast = (layer == 1) && (t == last_t);
#pragma unroll
            for (int j = 0; j < 2; j++) {
                int o = cg * 4 + 2 * j;
                float lo, hi; upk2(acc[j], lo, hi);
                float c0 = tanhfast(lo + cxv[2 * j]);
                float c1 = tanhfast(hi + cxv[2 * j + 1]);
                float u0 = uH[nl * 68 + o], u1 = uH[nl * 68 + o + 1];
                float h0 = hN[ng * 68 + o], h1 = hN[ng * 68 + o + 1];
                hv[2 * j] = u0 * h0 + (1.f - u0) * c0;
                hv[2 * j + 1] = u1 * h1 + (1.f - u1) * c1;
            }
            __syncthreads();   // all old-h reads done before overwrite
#pragma unroll
            for (int j = 0; j < 2; j++) {
                int o = cg * 4 + 2 * j;
                hN[ng * 68 + o] = hv[2 * j]; hN[ng * 68 + o + 1] = hv[2 * j + 1];
                hT[o * 34 + nl] = hv[2 * j]; hT[(o + 1) * 34 + nl] = hv[2 * j + 1];
            }
            float4 hq = make_float4(hv[0], hv[1], hv[2], hv[3]);
            __stcg((float4*)(g_xH + (size_t)self * 2048 + nl * 64 + cg * 4), hq);
            if (layer == 0)
                *(float4*)(g_Hseq + ((size_t)t * Bn + b) * 4096 + ng * 64 + cg * 4) = hq;
            if (isLast)
                *(float4*)(g_Last + (size_t)(b * 64 + ng) * 64 + cg * 4) = hq;
        }
        __syncthreads();
        if (tid == 0) {
            flag_release(fH_self);
            while (flag_acq(fH_peer) < t + 1) { }
        }
        __syncthreads();
        {   // import peer h half
            float4 v = __ldcg((const float4*)(g_xH + (size_t)peer * 2048) + tid);
            int row = tid >> 4, col = (tid * 4) & 63;
            int pn = (hf ^ 1) * 32 + row;
            *(float4*)&hN[pn * 68 + col] = v;
        }
        __syncthreads();
    }
}

// ---------- output head ----------
__global__ void k_head(const float* __restrict__ fcw, const float* __restrict__ fcb,
                       const float* __restrict__ idw, const float* __restrict__ idb,
                       float* __restrict__ out) {
    __shared__ float hb[4096];
    __shared__ float w[64 * 54];
    __shared__ float bias[54];
    int b = blockIdx.x, tid = threadIdx.x;
    for (int i = tid; i < 4096; i += 256) hb[i] = fmaxf(g_Last[b * 4096 + i], 0.f);
    for (int i = tid; i < 64 * 54; i += 256) {
        int k = i / 54, c = i % 54;
        w[i] = (c < 4) ? fcw[k * 4 + c] : idw[k * 50 + c - 4];
    }
    if (tid < 54) bias[tid] = (tid < 4) ? fcb[tid] : idb[tid - 4];
    __syncthreads();
    if (tid < 54) {
        float best = -INFINITY;
        for (int nn = 0; nn < 64; nn++) {
            float s = bias[tid];
            for (int k = 0; k < 64; k++) s += hb[nn * 64 + k] * w[k * 54 + tid];
            best = fmaxf(best, s);
        }
        if (tid < 4) out[b * 4 + tid] = best;
        else out[256 + b * 50 + tid - 4] = best;
    }
}

extern "C" void kernel_launch(void* const* d_in, const int* in_sizes, int n_in,
                              void* d_out, int out_size) {
    const float* xseq = (const float*)d_in[0];
    const int* seql = (const int*)d_in[1];
    const float* S0 = (const float*)d_in[2];
    const float* S1 = (const float*)d_in[3];
    const float* Wg0 = (const float*)d_in[4]; const float* bg0 = (const float*)d_in[5];
    const float* Wc0 = (const float*)d_in[6]; const float* bc0 = (const float*)d_in[7];
    const float* Wg1 = (const float*)d_in[8]; const float* bg1 = (const float*)d_in[9];
    const float* Wc1 = (const float*)d_in[10]; const float* bc1 = (const float*)d_in[11];
    const float* fcw = (const float*)d_in[12]; const float* fcb = (const float*)d_in[13];
    const float* idw = (const float*)d_in[14]; const float* idb = (const float*)d_in[15];
    float* out = (float*)d_out;

    const int SM_PRE = 192 * RSP * 4 + 64 * 192 * 4;   // 99840
    const int SM_REC = (8192 + 4352 + 4352 + 8192 + 2176 + 2176 + 2176 + 2176) * 4; // 135168
    cudaFuncSetAttribute(k_pre, cudaFuncAttributeMaxDynamicSharedMemorySize, SM_PRE);
    cudaFuncSetAttribute(k_recur, cudaFuncAttributeMaxDynamicSharedMemorySize, SM_REC);

    k_prep<<<1, 256>>>(S0, S1);
    k_pack<<<240, 256>>>(Wg0, Wc0, Wg1, Wc1);

    k_pre<<<dim3(2, Tn, Bn), 256, SM_PRE>>>(0, xseq, bg0, bc0);
    k_recur<<<dim3(2, Bn), 512, SM_REC>>>(0, seql);
    k_pre<<<dim3(2, Tn, Bn), 256, SM_PRE>>>(1, xseq, bg1, bc1);
    k_recur<<<dim3(2, Bn), 512, SM_REC>>>(1, seql);

    k_head<<<Bn, 256>>>(fcw, fcb, idw, idb, out);
}

// round 7
// speedup vs baseline: 1.7549x; 1.1365x over previous
#include <cuda_runtime.h>
#include <math.h>

typedef unsigned long long ull;
#define Tn 96
#define Bn 64

__device__ __forceinline__ ull pk2(float lo, float hi) {
    ull r; asm("mov.b64 %0,{%1,%2};" : "=l"(r) : "f"(lo), "f"(hi)); return r;
}
__device__ __forceinline__ void upk2(ull v, float &a, float &b) {
    asm("mov.b64 {%0,%1},%2;" : "=f"(a), "=f"(b) : "l"(v));
}
__device__ __forceinline__ void ffma2(ull &d, ull a, ull b) {
    asm("fma.rn.f32x2 %0,%1,%2,%0;" : "+l"(d) : "l"(a), "l"(b));
}
__device__ __forceinline__ float sigm(float x) { return 1.f / (1.f + __expf(-x)); }
__device__ __forceinline__ float tanhfast(float x) {
    float t = __expf(-2.f * fabsf(x));
    return copysignf((1.f - t) / (1.f + t), x);
}
__device__ __forceinline__ void flag_release(int* p) {
    asm volatile("red.release.gpu.global.add.s32 [%0], 1;" :: "l"(p) : "memory");
}
__device__ __forceinline__ int flag_acq(const int* p) {
    int v; asm volatile("ld.acquire.gpu.global.s32 %0, [%1];" : "=r"(v) : "l"(p) : "memory");
    return v;
}

// ---------- device-global scratch ----------
__device__ __align__(256) float g_Pt[4 * 4096];                   // [m][k][n] = P_{m+1}[n][k]
__device__ __align__(256) float g_WX[2][5 * 64 * 192];
__device__ __align__(256) float g_WgH[2][5 * 64 * 128];
__device__ __align__(256) float g_WcH[2][5 * 64 * 64];
__device__ __align__(256) float g_Gx[(size_t)Tn * Bn * 64 * 128];
__device__ __align__(256) float g_Cx[(size_t)Tn * Bn * 64 * 64];
__device__ __align__(256) float g_Hseq[(size_t)Tn * Bn * 4096];
__device__ __align__(256) float g_Last[Bn * 4096];
__device__ __align__(256) float g_xRH[128 * 2048];
__device__ __align__(256) float g_xH[128 * 2048];
__device__ __align__(256) int   g_flag[2][2][2][64];              // [layer][phase][hf][b]

// ---------- P matrices ----------
__global__ void k_prep(const float* __restrict__ S0, const float* __restrict__ S1) {
    __shared__ float s0[4096], s1[4096];
    int tid = threadIdx.x;
    for (int i = tid; i < 512; i += 256) ((int*)g_flag)[i] = 0;
    for (int i = tid; i < 4096; i += 256) { s0[i] = S0[i]; s1[i] = S1[i]; }
    __syncthreads();
    for (int i = tid; i < 4096; i += 256) {
        int n = i >> 6, k = i & 63;
        float a2 = 0.f, a3 = 0.f;
        for (int j = 0; j < 64; j++) {
            a2 += s0[n * 64 + j] * s0[j * 64 + k];
            a3 += s1[n * 64 + j] * s0[j * 64 + k];
        }
        g_Pt[k * 64 + n] = s0[i];
        g_Pt[4096 + k * 64 + n] = 2.f * a2 - (n == k ? 1.f : 0.f);
        g_Pt[2 * 4096 + k * 64 + n] = a3;
    }
    __syncthreads();
    for (int i = tid; i < 4096; i += 256) {
        int n = i >> 6, k = i & 63;
        float a4 = 0.f;
        for (int j = 0; j < 64; j++) a4 += s1[n * 64 + j] * g_Pt[2 * 4096 + k * 64 + j];
        g_Pt[3 * 4096 + k * 64 + n] = 2.f * a4 - s0[i];
    }
}

// ---------- weight repack ----------
__global__ void k_pack(const float* __restrict__ Wg0, const float* __restrict__ Wc0,
                       const float* __restrict__ Wg1, const float* __restrict__ Wc1) {
    const int WXsz = 5 * 64 * 192, WgHsz = 5 * 64 * 128, WcHsz = 5 * 64 * 64;
    const int PER_L = WXsz + WgHsz + WcHsz;
    for (int i = blockIdx.x * blockDim.x + threadIdx.x; i < 2 * PER_L; i += gridDim.x * blockDim.x) {
        int L = i / PER_L, r = i % PER_L;
        const float* Wg = L ? Wg1 : Wg0;
        const float* Wc = L ? Wc1 : Wc0;
        if (r < WXsz) {
            int m = r / (64 * 192), k = (r / 192) % 64, o = r % 192;
            g_WX[L][r] = (o < 128) ? Wg[(k * 5 + m) * 128 + o] : Wc[(k * 5 + m) * 64 + (o - 128)];
        } else if (r < WXsz + WgHsz) {
            int q = r - WXsz, m = q / (64 * 128), k = (q / 128) % 64, o = q % 128;
            g_WgH[L][q] = Wg[((64 + k) * 5 + m) * 128 + o];
        } else {
            int q = r - WXsz - WgHsz, m = q / 4096, k = (q / 64) % 64, o = q % 64;
            g_WcH[L][q] = Wc[((64 + k) * 5 + m) * 64 + o];
        }
    }
}

// ================= k_pre v2: one CTA per (t,b), transposed layouts =================
__device__ __forceinline__ void diffpre(const float* __restrict__ xN,
                                        const float* __restrict__ sP,
                                        float* __restrict__ xb,
                                        int pass, int grp, int n64) {
    int m = pass * 2 + (grp >> 2);
    int fg = grp & 3;
    const float* P = sP + m * 4096 + n64;
    const float* s = xN + fg * 16;
    ull d[8] = {0, 0, 0, 0, 0, 0, 0, 0};
    for (int k = 0; k < 64; k++) {
        float p = P[k * 64];
        ull p2 = pk2(p, p);
        const ulonglong2* hv = (const ulonglong2*)(s + k * 68);
        ulonglong2 a = hv[0], b = hv[1], c = hv[2], e = hv[3];
        ffma2(d[0], p2, a.x); ffma2(d[1], p2, a.y);
        ffma2(d[2], p2, b.x); ffma2(d[3], p2, b.y);
        ffma2(d[4], p2, c.x); ffma2(d[5], p2, c.y);
        ffma2(d[6], p2, e.x); ffma2(d[7], p2, e.y);
    }
    float* dst = xb + m * 4224 + fg * 16 * 66 + n64;
#pragma unroll
    for (int j = 0; j < 8; j++) {
        float x, y; upk2(d[j], x, y);
        dst[(2 * j) * 66] = x;
        dst[(2 * j + 1) * 66] = y;
    }
}

__device__ __forceinline__ void gemm_pre(const float* __restrict__ A,
                                         const float* __restrict__ B,
                                         ull* acc, int nl, int cg) {
    for (int k = 0; k < 64; k++) {
        float a0 = A[k * 66 + nl];
        float a1 = A[k * 66 + nl + 32];
        ull q0 = pk2(a0, a0), q1 = pk2(a1, a1);
        const ulonglong2* br = (const ulonglong2*)(B + k * 192 + cg * 12);
        ulonglong2 w0 = br[0], w1 = br[1], w2 = br[2];
        ffma2(acc[0], q0, w0.x); ffma2(acc[1], q0, w0.y);
        ffma2(acc[2], q0, w1.x); ffma2(acc[3], q0, w1.y);
        ffma2(acc[4], q0, w2.x); ffma2(acc[5], q0, w2.y);
        ffma2(acc[6], q1, w0.x); ffma2(acc[7], q1, w0.y);
        ffma2(acc[8], q1, w1.x); ffma2(acc[9], q1, w1.y);
        ffma2(acc[10], q1, w2.x); ffma2(acc[11], q1, w2.y);
    }
}

__global__ void __launch_bounds__(512, 1) k_pre(int layer, const float* __restrict__ xin,
                                                const float* __restrict__ bg,
                                                const float* __restrict__ bc) {
    extern __shared__ float sm[];
    float* xT = sm;             // [64f][66]
    float* xN = sm + 4224;      // [64n][68]
    float* xb = sm + 8576;      // [4][64f][66]
    float* Bs = sm + 25472;     // [64][192]
    float* sP = sm + 37760;     // [4][64][64]
    const int tid = threadIdx.x;
    const int t = blockIdx.x, b = blockIdx.y;
    const int nl = tid & 31, cg = tid >> 5;
    const int n64 = tid & 63, grp = tid >> 6;

    const float* src = layer ? (g_Hseq + ((size_t)t * Bn + b) * 4096)
                             : (xin + ((size_t)b * Tn + t) * 4096);
    for (int i = tid; i < 1024; i += 512) {
        float4 v = __ldg((const float4*)src + i);
        int n = i >> 4, fo = (i & 15) << 2;
        *(float4*)&xN[n * 68 + fo] = v;
        xT[fo * 66 + n] = v.x; xT[(fo + 1) * 66 + n] = v.y;
        xT[(fo + 2) * 66 + n] = v.z; xT[(fo + 3) * 66 + n] = v.w;
    }
    for (int i = tid * 4; i < 16384; i += 2048)
        *(float4*)&sP[i] = *(const float4*)&g_Pt[i];
    const float4* W4 = (const float4*)g_WX[layer];
    float4 pf[6];
#pragma unroll
    for (int j = 0; j < 6; j++) pf[j] = W4[tid + j * 512];
    __syncthreads();

    ull acc[12] = {0, 0, 0, 0, 0, 0, 0, 0, 0, 0, 0, 0};
#pragma unroll
    for (int m = 0; m < 5; m++) {
#pragma unroll
        for (int j = 0; j < 6; j++) ((float4*)Bs)[tid + j * 512] = pf[j];
        if (m < 4) {
#pragma unroll
            for (int j = 0; j < 6; j++) pf[j] = W4[(m + 1) * 3072 + tid + j * 512];
        }
        if (m == 0) diffpre(xN, sP, xb, 0, grp, n64);
        if (m == 1) diffpre(xN, sP, xb, 1, grp, n64);
        __syncthreads();
        gemm_pre((m == 0) ? xT : (xb + (m - 1) * 4224), Bs, acc, nl, cg);
        __syncthreads();
    }

    size_t gb = ((size_t)t * Bn + b) * 64;
#pragma unroll
    for (int h = 0; h < 2; h++) {
        int n = nl + h * 32;
        float* Gp = g_Gx + (gb + n) * 128;
        float* Cp = g_Cx + (gb + n) * 64;
#pragma unroll
        for (int j = 0; j < 6; j++) {
            int o = cg * 12 + 2 * j;
            float lo, hi; upk2(acc[h * 6 + j], lo, hi);
            if (o < 128) {
                Gp[o] = lo + __ldg(bg + o);
                Gp[o + 1] = hi + __ldg(bg + o + 1);
            } else {
                Cp[o - 128] = lo + __ldg(bc + o - 128);
                Cp[o - 127] = hi + __ldg(bc + o - 127);
            }
        }
    }
}

// ================= recur v4: 2 CTAs/batch, double-buffered tiles, 2m diffusion =================
__device__ __forceinline__ void diff2(const float* __restrict__ srcN,
                                      const float* __restrict__ sPh,
                                      float* __restrict__ xb,
                                      int pass, int w, int nl) {
    int m = pass * 2 + (w >> 3);
    int fg = w & 7;
    const float* P = sPh + m * 2048 + nl;
    const float* s = srcN + fg * 8;
    ull d0 = 0, d1 = 0, d2 = 0, d3 = 0;
    for (int k = 0; k < 64; k++) {
        float p = P[k * 32];
        ull p2 = pk2(p, p);
        const ulonglong2* hv = (const ulonglong2*)(s + k * 68);
        ulonglong2 a = hv[0], b = hv[1];
        ffma2(d0, p2, a.x); ffma2(d1, p2, a.y);
        ffma2(d2, p2, b.x); ffma2(d3, p2, b.y);
    }
    float* dst = xb + m * 2176 + fg * 8 * 34 + nl;
    float x, y;
    upk2(d0, x, y); dst[0] = x;   dst[34] = y;
    upk2(d1, x, y); dst[68] = x;  dst[102] = y;
    upk2(d2, x, y); dst[136] = x; dst[170] = y;
    upk2(d3, x, y); dst[204] = x; dst[238] = y;
}

__device__ __forceinline__ void gemm_gate(const float* __restrict__ A,
                                          const float* __restrict__ B,
                                          ull* acc, int nl, int cg) {
    for (int k = 0; k < 64; k++) {
        float a = A[k * 34 + nl];
        ull a2 = pk2(a, a);
        const ulonglong2* br = (const ulonglong2*)(B + k * 128 + cg * 8);
        ulonglong2 w0 = br[0], w1 = br[1];
        ffma2(acc[0], a2, w0.x); ffma2(acc[1], a2, w0.y);
        ffma2(acc[2], a2, w1.x); ffma2(acc[3], a2, w1.y);
    }
}
__device__ __forceinline__ void gemm_cand(const float* __restrict__ A,
                                          const float* __restrict__ B,
                                          ull* acc, int nl, int cg) {
    for (int k = 0; k < 64; k++) {
        float a = A[k * 34 + nl];
        ull a2 = pk2(a, a);
        ulonglong2 w = *(const ulonglong2*)(B + k * 64 + cg * 4);
        ffma2(acc[0], a2, w.x); ffma2(acc[1], a2, w.y);
    }
}

__global__ void __launch_bounds__(512, 1) k_recur(int layer, const int* __restrict__ seql) {
    extern __shared__ float sm[];
    float* Bs  = sm;                  // [2][8192]
    float* hN  = sm + 16384;          // [64][68]
    float* rhN = hN + 4352;           // [64][68]
    float* sPh = rhN + 4352;          // [4][64][32]
    float* hT  = sPh + 8192;          // [64f][34]
    float* rhT = hT + 2176;           // [64f][34]
    float* uT  = rhT + 2176;          // [64o][34]
    float* xb  = uT + 2176;           // [4][64f][34]

    const int tid = threadIdx.x;
    const int hf = blockIdx.x;
    const int b = blockIdx.y;
    const int nl = tid & 31;
    const int cg = tid >> 5;          // warp id 0..15
    const int ng = hf * 32 + nl;
    const int peer = b * 2 + (hf ^ 1);
    const int self = b * 2 + hf;

    for (int i = tid; i < 8192; i += 512) {
        int m = i >> 11, r = i & 2047, k = r >> 5, nn = r & 31;
        sPh[i] = g_Pt[m * 4096 + k * 64 + hf * 32 + nn];
    }
    for (int i = tid; i < 64 * 68; i += 512) hN[i] = 0.f;
    for (int i = tid; i < 64 * 34; i += 512) hT[i] = 0.f;
    __syncthreads();

    const float4* Wg4 = (const float4*)g_WgH[layer];
    const float4* Wc4 = (const float4*)g_WcH[layer];
    int* fRH_self = &g_flag[layer][0][hf][b];
    int* fRH_peer = &g_flag[layer][0][hf ^ 1][b];
    int* fH_self  = &g_flag[layer][1][hf][b];
    int* fH_peer  = &g_flag[layer][1][hf ^ 1][b];
    const int last_t = seql[b] - 1;

    for (int t = 0; t < Tn; t++) {
        // ================= GATE =================
        {
            const float* GxP = g_Gx + (((size_t)t * Bn + b) * 64 + ng) * 128 + cg * 8;
            float4 gx0 = __ldg((const float4*)GxP);
            float4 gx1 = __ldg((const float4*)GxP + 1);
            ull acc[4] = {0, 0, 0, 0};
            float4 pf0 = Wg4[tid], pf1 = Wg4[tid + 512], pf2 = Wg4[tid + 1024], pf3 = Wg4[tid + 1536];
            // prologue: Bs buf0 <- m0, diff pass0
            ((float4*)Bs)[tid] = pf0; ((float4*)Bs)[tid + 512] = pf1;
            ((float4*)Bs)[tid + 1024] = pf2; ((float4*)Bs)[tid + 1536] = pf3;
            pf0 = Wg4[2048 + tid]; pf1 = Wg4[2048 + tid + 512];
            pf2 = Wg4[2048 + tid + 1024]; pf3 = Wg4[2048 + tid + 1536];
            diff2(hN, sPh, xb, 0, cg, nl);
            __syncthreads();
#pragma unroll
            for (int m = 0; m < 5; m++) {
                gemm_gate((m == 0) ? hT : (xb + (m - 1) * 2176), Bs + (m & 1) * 8192, acc, nl, cg);
                if (m < 4) {
                    float4* d = (float4*)(Bs + ((m + 1) & 1) * 8192);
                    d[tid] = pf0; d[tid + 512] = pf1; d[tid + 1024] = pf2; d[tid + 1536] = pf3;
                    if (m < 3) {
                        pf0 = Wg4[(m + 2) * 2048 + tid];        pf1 = Wg4[(m + 2) * 2048 + tid + 512];
                        pf2 = Wg4[(m + 2) * 2048 + tid + 1024]; pf3 = Wg4[(m + 2) * 2048 + tid + 1536];
                    }
                    if (m == 0) diff2(hN, sPh, xb, 1, cg, nl);
                    __syncthreads();
                }
            }
            float gx[8] = {gx0.x, gx0.y, gx0.z, gx0.w, gx1.x, gx1.y, gx1.z, gx1.w};
            if (cg < 8) {
                float rv[8];
#pragma unroll
                for (int j = 0; j < 4; j++) {
                    int o = cg * 8 + 2 * j;
                    float lo, hi; upk2(acc[j], lo, hi);
                    float h0 = hT[o * 34 + nl], h1 = hT[(o + 1) * 34 + nl];
                    float r0 = sigm(lo + gx[2 * j]) * h0;
                    float r1 = sigm(hi + gx[2 * j + 1]) * h1;
                    rhN[ng * 68 + o] = r0; rhN[ng * 68 + o + 1] = r1;
                    rhT[o * 34 + nl] = r0; rhT[(o + 1) * 34 + nl] = r1;
                    rv[2 * j] = r0; rv[2 * j + 1] = r1;
                }
                float4* dst = (float4*)(g_xRH + (size_t)self * 2048 + nl * 64 + cg * 8);
                __stcg(dst, make_float4(rv[0], rv[1], rv[2], rv[3]));
                __stcg(dst + 1, make_float4(rv[4], rv[5], rv[6], rv[7]));
            } else {
#pragma unroll
                for (int j = 0; j < 4; j++) {
                    int o = cg * 8 + 2 * j;
                    float lo, hi; upk2(acc[j], lo, hi);
                    uT[(o - 64) * 34 + nl] = sigm(lo + gx[2 * j]);
                    uT[(o - 63) * 34 + nl] = sigm(hi + gx[2 * j + 1]);
                }
            }
        }
        __syncthreads();
        if (tid == 0) {
            flag_release(fRH_self);
            while (flag_acq(fRH_peer) < t + 1) { }
        }
        __syncthreads();
        {
            float4 v = __ldcg((const float4*)(g_xRH + (size_t)peer * 2048) + tid);
            int row = tid >> 4, col = (tid * 4) & 63;
            int pn = (hf ^ 1) * 32 + row;
            *(float4*)&rhN[pn * 68 + col] = v;
        }
        __syncthreads();

        // ================= CAND =================
        {
            const float* CxP = g_Cx + (((size_t)t * Bn + b) * 64 + ng) * 64 + cg * 4;
            float4 cx = __ldg((const float4*)CxP);
            ull acc[2] = {0, 0};
            float4 pc0 = Wc4[tid], pc1 = Wc4[tid + 512];
            ((float4*)Bs)[tid] = pc0; ((float4*)Bs)[tid + 512] = pc1;
            pc0 = Wc4[1024 + tid]; pc1 = Wc4[1024 + tid + 512];
            diff2(rhN, sPh, xb, 0, cg, nl);
            __syncthreads();
#pragma unroll
            for (int m = 0; m < 5; m++) {
                gemm_cand((m == 0) ? rhT : (xb + (m - 1) * 2176), Bs + (m & 1) * 8192, acc, nl, cg);
                if (m < 4) {
                    float4* d = (float4*)(Bs + ((m + 1) & 1) * 8192);
                    d[tid] = pc0; d[tid + 512] = pc1;
                    if (m < 3) {
                        pc0 = Wc4[(m + 2) * 1024 + tid];
                        pc1 = Wc4[(m + 2) * 1024 + tid + 512];
                    }
                    if (m == 0) diff2(rhN, sPh, xb, 1, cg, nl);
                    __syncthreads();
                }
            }
            float cxv[4] = {cx.x, cx.y, cx.z, cx.w};
            float hv[4];
            bool isLast = (layer == 1) && (t == last_t);
#pragma unroll
            for (int j = 0; j < 2; j++) {
                int o = cg * 4 + 2 * j;
                float lo, hi; upk2(acc[j], lo, hi);
                float c0 = tanhfast(lo + cxv[2 * j]);
                float c1 = tanhfast(hi + cxv[2 * j + 1]);
                float u0 = uT[o * 34 + nl], u1 = uT[(o + 1) * 34 + nl];
                float h0 = hT[o * 34 + nl], h1 = hT[(o + 1) * 34 + nl];
                hv[2 * j] = u0 * h0 + (1.f - u0) * c0;
                hv[2 * j + 1] = u1 * h1 + (1.f - u1) * c1;
            }
#pragma unroll
            for (int j = 0; j < 2; j++) {
                int o = cg * 4 + 2 * j;
                hN[ng * 68 + o] = hv[2 * j]; hN[ng * 68 + o + 1] = hv[2 * j + 1];
                hT[o * 34 + nl] = hv[2 * j]; hT[(o + 1) * 34 + nl] = hv[2 * j + 1];
            }
            float4 hq = make_float4(hv[0], hv[1], hv[2], hv[3]);
            __stcg((float4*)(g_xH + (size_t)self * 2048 + nl * 64 + cg * 4), hq);
            if (layer == 0)
                *(float4*)(g_Hseq + ((size_t)t * Bn + b) * 4096 + ng * 64 + cg * 4) = hq;
            if (isLast)
                *(float4*)(g_Last + (size_t)(b * 64 + ng) * 64 + cg * 4) = hq;
        }
        __syncthreads();
        if (tid == 0) {
            flag_release(fH_self);
            while (flag_acq(fH_peer) < t + 1) { }
        }
        __syncthreads();
        {
            float4 v = __ldcg((const float4*)(g_xH + (size_t)peer * 2048) + tid);
            int row = tid >> 4, col = (tid * 4) & 63;
            int pn = (hf ^ 1) * 32 + row;
            *(float4*)&hN[pn * 68 + col] = v;
        }
        __syncthreads();
    }
}

// ---------- output head ----------
__global__ void k_head(const float* __restrict__ fcw, const float* __restrict__ fcb,
                       const float* __restrict__ idw, const float* __restrict__ idb,
                       float* __restrict__ out) {
    __shared__ float hb[4096];
    __shared__ float w[64 * 54];
    __shared__ float bias[54];
    int b = blockIdx.x, tid = threadIdx.x;
    for (int i = tid; i < 4096; i += 256) hb[i] = fmaxf(g_Last[b * 4096 + i], 0.f);
    for (int i = tid; i < 64 * 54; i += 256) {
        int k = i / 54, c = i % 54;
        w[i] = (c < 4) ? fcw[k * 4 + c] : idw[k * 50 + c - 4];
    }
    if (tid < 54) bias[tid] = (tid < 4) ? fcb[tid] : idb[tid - 4];
    __syncthreads();
    if (tid < 54) {
        float best = -INFINITY;
        for (int nn = 0; nn < 64; nn++) {
            float s = bias[tid];
            for (int k = 0; k < 64; k++) s += hb[nn * 64 + k] * w[k * 54 + tid];
            best = fmaxf(best, s);
        }
        if (tid < 4) out[b * 4 + tid] = best;
        else out[256 + b * 50 + tid - 4] = best;
    }
}

extern "C" void kernel_launch(void* const* d_in, const int* in_sizes, int n_in,
                              void* d_out, int out_size) {
    const float* xseq = (const float*)d_in[0];
    const int* seql = (const int*)d_in[1];
    const float* S0 = (const float*)d_in[2];
    const float* S1 = (const float*)d_in[3];
    const float* Wg0 = (const float*)d_in[4]; const float* bg0 = (const float*)d_in[5];
    const float* Wc0 = (const float*)d_in[6]; const float* bc0 = (const float*)d_in[7];
    const float* Wg1 = (const float*)d_in[8]; const float* bg1 = (const float*)d_in[9];
    const float* Wc1 = (const float*)d_in[10]; const float* bc1 = (const float*)d_in[11];
    const float* fcw = (const float*)d_in[12]; const float* fcb = (const float*)d_in[13];
    const float* idw = (const float*)d_in[14]; const float* idb = (const float*)d_in[15];
    float* out = (float*)d_out;

    const int SM_PRE = (4224 + 4352 + 16896 + 12288 + 16384) * 4;   // 216576
    const int SM_REC = (16384 + 4352 + 4352 + 8192 + 2176 + 2176 + 2176 + 8704) * 4; // 194048
    cudaFuncSetAttribute(k_pre, cudaFuncAttributeMaxDynamicSharedMemorySize, SM_PRE);
    cudaFuncSetAttribute(k_recur, cudaFuncAttributeMaxDynamicSharedMemorySize, SM_REC);

    k_prep<<<1, 256>>>(S0, S1);
    k_pack<<<240, 256>>>(Wg0, Wc0, Wg1, Wc1);

    k_pre<<<dim3(Tn, Bn), 512, SM_PRE>>>(0, xseq, bg0, bc0);
    k_recur<<<dim3(2, Bn), 512, SM_REC>>>(0, seql);
    k_pre<<<dim3(Tn, Bn), 512, SM_PRE>>>(1, xseq, bg1, bc1);
    k_recur<<<dim3(2, Bn), 512, SM_REC>>>(1, seql);

    k_head<<<Bn, 256>>>(fcw, fcb, idw, idb, out);
}

// round 8
// speedup vs baseline: 1.8200x; 1.0371x over previous
#include <cuda_runtime.h>
#include <math.h>

typedef unsigned long long ull;
#define Tn 96
#define Bn 64

__device__ __forceinline__ ull pk2(float lo, float hi) {
    ull r; asm("mov.b64 %0,{%1,%2};" : "=l"(r) : "f"(lo), "f"(hi)); return r;
}
__device__ __forceinline__ void upk2(ull v, float &a, float &b) {
    asm("mov.b64 {%0,%1},%2;" : "=f"(a), "=f"(b) : "l"(v));
}
__device__ __forceinline__ void ffma2(ull &d, ull a, ull b) {
    asm("fma.rn.f32x2 %0,%1,%2,%0;" : "+l"(d) : "l"(a), "l"(b));
}
__device__ __forceinline__ float sigm(float x) { return 1.f / (1.f + __expf(-x)); }
__device__ __forceinline__ float tanhfast(float x) {
    float t = __expf(-2.f * fabsf(x));
    return copysignf((1.f - t) / (1.f + t), x);
}
__device__ __forceinline__ unsigned s2u(const void* p) {
    unsigned a;
    asm("{ .reg .u64 t; cvta.to.shared.u64 t, %1; cvt.u32.u64 %0, t; }" : "=r"(a) : "l"(p));
    return a;
}
__device__ __forceinline__ unsigned mapa_rank(unsigned a, unsigned rank) {
    unsigned r; asm("mapa.shared::cluster.u32 %0, %1, %2;" : "=r"(r) : "r"(a), "r"(rank));
    return r;
}
__device__ __forceinline__ void st_rem_v4(unsigned a, float4 v) {
    asm volatile("st.shared::cluster.v4.f32 [%0], {%1,%2,%3,%4};"
                 :: "r"(a), "f"(v.x), "f"(v.y), "f"(v.z), "f"(v.w) : "memory");
}
#define CLUSTER_SYNC() do { \
    asm volatile("barrier.cluster.arrive.aligned;" ::: "memory"); \
    asm volatile("barrier.cluster.wait.aligned;" ::: "memory"); \
} while (0)

// ---------- device-global scratch ----------
__device__ __align__(256) float g_Pt[4 * 4096];                   // [m][k][n] = P_{m+1}[n][k]
__device__ __align__(256) float g_WX[2][5 * 64 * 192];
__device__ __align__(256) float g_WgH[2][5 * 64 * 128];
__device__ __align__(256) float g_WcH[2][5 * 64 * 64];
__device__ __align__(256) float g_Gx[(size_t)Tn * Bn * 64 * 128];
__device__ __align__(256) float g_Cx[(size_t)Tn * Bn * 64 * 64];
__device__ __align__(256) float g_Hseq[(size_t)Tn * Bn * 4096];
__device__ __align__(256) float g_Last[Bn * 4096];

// ---------- P matrices ----------
__global__ void k_prep(const float* __restrict__ S0, const float* __restrict__ S1) {
    __shared__ float s0[4096], s1[4096];
    int tid = threadIdx.x;
    for (int i = tid; i < 4096; i += 256) { s0[i] = S0[i]; s1[i] = S1[i]; }
    __syncthreads();
    for (int i = tid; i < 4096; i += 256) {
        int n = i >> 6, k = i & 63;
        float a2 = 0.f, a3 = 0.f;
        for (int j = 0; j < 64; j++) {
            a2 += s0[n * 64 + j] * s0[j * 64 + k];
            a3 += s1[n * 64 + j] * s0[j * 64 + k];
        }
        g_Pt[k * 64 + n] = s0[i];
        g_Pt[4096 + k * 64 + n] = 2.f * a2 - (n == k ? 1.f : 0.f);
        g_Pt[2 * 4096 + k * 64 + n] = a3;
    }
    __syncthreads();
    for (int i = tid; i < 4096; i += 256) {
        int n = i >> 6, k = i & 63;
        float a4 = 0.f;
        for (int j = 0; j < 64; j++) a4 += s1[n * 64 + j] * g_Pt[2 * 4096 + k * 64 + j];
        g_Pt[3 * 4096 + k * 64 + n] = 2.f * a4 - s0[i];
    }
}

// ---------- weight repack ----------
__global__ void k_pack(const float* __restrict__ Wg0, const float* __restrict__ Wc0,
                       const float* __restrict__ Wg1, const float* __restrict__ Wc1) {
    const int WXsz = 5 * 64 * 192, WgHsz = 5 * 64 * 128, WcHsz = 5 * 64 * 64;
    const int PER_L = WXsz + WgHsz + WcHsz;
    for (int i = blockIdx.x * blockDim.x + threadIdx.x; i < 2 * PER_L; i += gridDim.x * blockDim.x) {
        int L = i / PER_L, r = i % PER_L;
        const float* Wg = L ? Wg1 : Wg0;
        const float* Wc = L ? Wc1 : Wc0;
        if (r < WXsz) {
            int m = r / (64 * 192), k = (r / 192) % 64, o = r % 192;
            g_WX[L][r] = (o < 128) ? Wg[(k * 5 + m) * 128 + o] : Wc[(k * 5 + m) * 64 + (o - 128)];
        } else if (r < WXsz + WgHsz) {
            int q = r - WXsz, m = q / (64 * 128), k = (q / 128) % 64, o = q % 128;
            g_WgH[L][q] = Wg[((64 + k) * 5 + m) * 128 + o];
        } else {
            int q = r - WXsz - WgHsz, m = q / 4096, k = (q / 64) % 64, o = q % 64;
            g_WcH[L][q] = Wc[((64 + k) * 5 + m) * 64 + o];
        }
    }
}

// ================= k_pre: one CTA per (t,b) =================
__device__ __forceinline__ void diffpre(const float* __restrict__ xN,
                                        const float* __restrict__ sP,
                                        float* __restrict__ xb,
                                        int pass, int grp, int n64) {
    int m = pass * 2 + (grp >> 2);
    int fg = grp & 3;
    const float* P = sP + m * 4096 + n64;
    const float* s = xN + fg * 16;
    ull d[8] = {0, 0, 0, 0, 0, 0, 0, 0};
    for (int k = 0; k < 64; k++) {
        float p = P[k * 64];
        ull p2 = pk2(p, p);
        const ulonglong2* hv = (const ulonglong2*)(s + k * 68);
        ulonglong2 a = hv[0], b = hv[1], c = hv[2], e = hv[3];
        ffma2(d[0], p2, a.x); ffma2(d[1], p2, a.y);
        ffma2(d[2], p2, b.x); ffma2(d[3], p2, b.y);
        ffma2(d[4], p2, c.x); ffma2(d[5], p2, c.y);
        ffma2(d[6], p2, e.x); ffma2(d[7], p2, e.y);
    }
    float* dst = xb + m * 4224 + fg * 16 * 66 + n64;
#pragma unroll
    for (int j = 0; j < 8; j++) {
        float x, y; upk2(d[j], x, y);
        dst[(2 * j) * 66] = x;
        dst[(2 * j + 1) * 66] = y;
    }
}

__device__ __forceinline__ void gemm_pre(const float* __restrict__ A,
                                         const float* __restrict__ B,
                                         ull* acc, int nl, int cg) {
    for (int k = 0; k < 64; k++) {
        float a0 = A[k * 66 + nl];
        float a1 = A[k * 66 + nl + 32];
        ull q0 = pk2(a0, a0), q1 = pk2(a1, a1);
        const ulonglong2* br = (const ulonglong2*)(B + k * 192 + cg * 12);
        ulonglong2 w0 = br[0], w1 = br[1], w2 = br[2];
        ffma2(acc[0], q0, w0.x); ffma2(acc[1], q0, w0.y);
        ffma2(acc[2], q0, w1.x); ffma2(acc[3], q0, w1.y);
        ffma2(acc[4], q0, w2.x); ffma2(acc[5], q0, w2.y);
        ffma2(acc[6], q1, w0.x); ffma2(acc[7], q1, w0.y);
        ffma2(acc[8], q1, w1.x); ffma2(acc[9], q1, w1.y);
        ffma2(acc[10], q1, w2.x); ffma2(acc[11], q1, w2.y);
    }
}

__global__ void __launch_bounds__(512, 1) k_pre(int layer, const float* __restrict__ xin,
                                                const float* __restrict__ bg,
                                                const float* __restrict__ bc) {
    extern __shared__ float sm[];
    float* xT = sm;             // [64f][66]
    float* xN = sm + 4224;      // [64n][68]
    float* xb = sm + 8576;      // [4][64f][66]
    float* Bs = sm + 25472;     // [64][192]
    float* sP = sm + 37760;     // [4][64][64]
    const int tid = threadIdx.x;
    const int t = blockIdx.x, b = blockIdx.y;
    const int nl = tid & 31, cg = tid >> 5;
    const int n64 = tid & 63, grp = tid >> 6;

    const float* src = layer ? (g_Hseq + ((size_t)t * Bn + b) * 4096)
                             : (xin + ((size_t)b * Tn + t) * 4096);
    for (int i = tid; i < 1024; i += 512) {
        float4 v = __ldg((const float4*)src + i);
        int n = i >> 4, fo = (i & 15) << 2;
        *(float4*)&xN[n * 68 + fo] = v;
        xT[fo * 66 + n] = v.x; xT[(fo + 1) * 66 + n] = v.y;
        xT[(fo + 2) * 66 + n] = v.z; xT[(fo + 3) * 66 + n] = v.w;
    }
    for (int i = tid * 4; i < 16384; i += 2048)
        *(float4*)&sP[i] = *(const float4*)&g_Pt[i];
    const float4* W4 = (const float4*)g_WX[layer];
    float4 pf[6];
#pragma unroll
    for (int j = 0; j < 6; j++) pf[j] = W4[tid + j * 512];
    __syncthreads();

    ull acc[12] = {0, 0, 0, 0, 0, 0, 0, 0, 0, 0, 0, 0};
#pragma unroll
    for (int m = 0; m < 5; m++) {
#pragma unroll
        for (int j = 0; j < 6; j++) ((float4*)Bs)[tid + j * 512] = pf[j];
        if (m < 4) {
#pragma unroll
            for (int j = 0; j < 6; j++) pf[j] = W4[(m + 1) * 3072 + tid + j * 512];
        }
        if (m == 0) diffpre(xN, sP, xb, 0, grp, n64);
        if (m == 1) diffpre(xN, sP, xb, 1, grp, n64);
        __syncthreads();
        gemm_pre((m == 0) ? xT : (xb + (m - 1) * 4224), Bs, acc, nl, cg);
        __syncthreads();
    }

    size_t gb = ((size_t)t * Bn + b) * 64;
#pragma unroll
    for (int h = 0; h < 2; h++) {
        int n = nl + h * 32;
        float* Gp = g_Gx + (gb + n) * 128;
        float* Cp = g_Cx + (gb + n) * 64;
#pragma unroll
        for (int j = 0; j < 6; j++) {
            int o = cg * 12 + 2 * j;
            float lo, hi; upk2(acc[h * 6 + j], lo, hi);
            if (o < 128) {
                Gp[o] = lo + __ldg(bg + o);
                Gp[o + 1] = hi + __ldg(bg + o + 1);
            } else {
                Cp[o - 128] = lo + __ldg(bc + o - 128);
                Cp[o - 127] = hi + __ldg(bc + o - 127);
            }
        }
    }
}

// ================= recur v5: 2-CTA cluster per batch, DSMEM exchange =================
__device__ __forceinline__ void diff2(const float* __restrict__ srcN,
                                      const float* __restrict__ sPh,
                                      float* __restrict__ xb,
                                      int pass, int w, int nl) {
    int m = pass * 2 + (w >> 3);
    int fg = w & 7;
    const float* P = sPh + m * 2048 + nl;
    const float* s = srcN + fg * 8;
    ull d0 = 0, d1 = 0, d2 = 0, d3 = 0;
    for (int k = 0; k < 64; k++) {
        float p = P[k * 32];
        ull p2 = pk2(p, p);
        const ulonglong2* hv = (const ulonglong2*)(s + k * 68);
        ulonglong2 a = hv[0], b = hv[1];
        ffma2(d0, p2, a.x); ffma2(d1, p2, a.y);
        ffma2(d2, p2, b.x); ffma2(d3, p2, b.y);
    }
    float* dst = xb + m * 2176 + fg * 8 * 34 + nl;
    float x, y;
    upk2(d0, x, y); dst[0] = x;   dst[34] = y;
    upk2(d1, x, y); dst[68] = x;  dst[102] = y;
    upk2(d2, x, y); dst[136] = x; dst[170] = y;
    upk2(d3, x, y); dst[204] = x; dst[238] = y;
}

__device__ __forceinline__ void gemm_gate(const float* __restrict__ A,
                                          const float* __restrict__ B,
                                          ull* acc, int nl, int cg) {
    for (int k = 0; k < 64; k++) {
        float a = A[k * 34 + nl];
        ull a2 = pk2(a, a);
        const ulonglong2* br = (const ulonglong2*)(B + k * 128 + cg * 8);
        ulonglong2 w0 = br[0], w1 = br[1];
        ffma2(acc[0], a2, w0.x); ffma2(acc[1], a2, w0.y);
        ffma2(acc[2], a2, w1.x); ffma2(acc[3], a2, w1.y);
    }
}
__device__ __forceinline__ void gemm_cand(const float* __restrict__ A,
                                          const float* __restrict__ B,
                                          ull* acc, int nl, int cg) {
    for (int k = 0; k < 64; k++) {
        float a = A[k * 34 + nl];
        ull a2 = pk2(a, a);
        ulonglong2 w = *(const ulonglong2*)(B + k * 64 + cg * 4);
        ffma2(acc[0], a2, w.x); ffma2(acc[1], a2, w.y);
    }
}

__global__ void __launch_bounds__(512, 1) __cluster_dims__(2, 1, 1)
k_recur(int layer, const int* __restrict__ seql) {
    extern __shared__ float sm[];
    float* Bs  = sm;                  // [2][8192]
    float* hN  = sm + 16384;          // [64][68]
    float* rhN = hN + 4352;           // [64][68]
    float* sPh = rhN + 4352;          // [4][64][32]
    float* hT  = sPh + 8192;          // [64f][34]
    float* rhT = hT + 2176;           // [64f][34]
    float* uT  = rhT + 2176;          // [64o][34]
    float* xb  = uT + 2176;           // [4][64f][34]

    const int tid = threadIdx.x;
    const int hf = blockIdx.x & 1;    // cluster rank
    const int b = blockIdx.y;
    const int nl = tid & 31;
    const int cg = tid >> 5;          // warp id 0..15
    const int ng = hf * 32 + nl;
    const unsigned peer_rank = hf ^ 1;

    for (int i = tid; i < 8192; i += 512) {
        int m = i >> 11, r = i & 2047, k = r >> 5, nn = r & 31;
        sPh[i] = g_Pt[m * 4096 + k * 64 + hf * 32 + nn];
    }
    for (int i = tid; i < 64 * 68; i += 512) hN[i] = 0.f;
    for (int i = tid; i < 64 * 34; i += 512) hT[i] = 0.f;
    const unsigned rhN_rem_base = mapa_rank(s2u(&rhN[ng * 68]), peer_rank);
    const unsigned hN_rem_base  = mapa_rank(s2u(&hN[ng * 68]), peer_rank);
    CLUSTER_SYNC();   // both CTAs initialized before any DSMEM traffic

    const float4* Wg4 = (const float4*)g_WgH[layer];
    const float4* Wc4 = (const float4*)g_WcH[layer];
    const int last_t = seql[b] - 1;

    for (int t = 0; t < Tn; t++) {
        // ================= GATE =================
        {
            const float* GxP = g_Gx + (((size_t)t * Bn + b) * 64 + ng) * 128 + cg * 8;
            float4 gx0 = __ldg((const float4*)GxP);
            float4 gx1 = __ldg((const float4*)GxP + 1);
            ull acc[4] = {0, 0, 0, 0};
            float4 pf0 = Wg4[tid], pf1 = Wg4[tid + 512], pf2 = Wg4[tid + 1024], pf3 = Wg4[tid + 1536];
            ((float4*)Bs)[tid] = pf0; ((float4*)Bs)[tid + 512] = pf1;
            ((float4*)Bs)[tid + 1024] = pf2; ((float4*)Bs)[tid + 1536] = pf3;
            pf0 = Wg4[2048 + tid]; pf1 = Wg4[2048 + tid + 512];
            pf2 = Wg4[2048 + tid + 1024]; pf3 = Wg4[2048 + tid + 1536];
            diff2(hN, sPh, xb, 0, cg, nl);
            __syncthreads();
#pragma unroll
            for (int m = 0; m < 5; m++) {
                gemm_gate((m == 0) ? hT : (xb + (m - 1) * 2176), Bs + (m & 1) * 8192, acc, nl, cg);
                if (m < 4) {
                    float4* d = (float4*)(Bs + ((m + 1) & 1) * 8192);
                    d[tid] = pf0; d[tid + 512] = pf1; d[tid + 1024] = pf2; d[tid + 1536] = pf3;
                    if (m < 3) {
                        pf0 = Wg4[(m + 2) * 2048 + tid];        pf1 = Wg4[(m + 2) * 2048 + tid + 512];
                        pf2 = Wg4[(m + 2) * 2048 + tid + 1024]; pf3 = Wg4[(m + 2) * 2048 + tid + 1536];
                    }
                    if (m == 0) diff2(hN, sPh, xb, 1, cg, nl);
                    __syncthreads();
                }
            }
            float gx[8] = {gx0.x, gx0.y, gx0.z, gx0.w, gx1.x, gx1.y, gx1.z, gx1.w};
            if (cg < 8) {
                float rv[8];
#pragma unroll
                for (int j = 0; j < 4; j++) {
                    int o = cg * 8 + 2 * j;
                    float lo, hi; upk2(acc[j], lo, hi);
                    float h0 = hT[o * 34 + nl], h1 = hT[(o + 1) * 34 + nl];
                    float r0 = sigm(lo + gx[2 * j]) * h0;
                    float r1 = sigm(hi + gx[2 * j + 1]) * h1;
                    rhN[ng * 68 + o] = r0; rhN[ng * 68 + o + 1] = r1;
                    rhT[o * 34 + nl] = r0; rhT[(o + 1) * 34 + nl] = r1;
                    rv[2 * j] = r0; rv[2 * j + 1] = r1;
                }
                unsigned rem = rhN_rem_base + cg * 32;   // cg*8 floats
                st_rem_v4(rem, make_float4(rv[0], rv[1], rv[2], rv[3]));
                st_rem_v4(rem + 16, make_float4(rv[4], rv[5], rv[6], rv[7]));
            } else {
#pragma unroll
                for (int j = 0; j < 4; j++) {
                    int o = cg * 8 + 2 * j;
                    float lo, hi; upk2(acc[j], lo, hi);
                    uT[(o - 64) * 34 + nl] = sigm(lo + gx[2 * j]);
                    uT[(o - 63) * 34 + nl] = sigm(hi + gx[2 * j + 1]);
                }
            }
        }
        CLUSTER_SYNC();   // rh halves exchanged, all smem writes visible

        // ================= CAND =================
        {
            const float* CxP = g_Cx + (((size_t)t * Bn + b) * 64 + ng) * 64 + cg * 4;
            float4 cx = __ldg((const float4*)CxP);
            ull acc[2] = {0, 0};
            float4 pc0 = Wc4[tid], pc1 = Wc4[tid + 512];
            ((float4*)Bs)[tid] = pc0; ((float4*)Bs)[tid + 512] = pc1;
            pc0 = Wc4[1024 + tid]; pc1 = Wc4[1024 + tid + 512];
            diff2(rhN, sPh, xb, 0, cg, nl);
            __syncthreads();
#pragma unroll
            for (int m = 0; m < 5; m++) {
                gemm_cand((m == 0) ? rhT : (xb + (m - 1) * 2176), Bs + (m & 1) * 8192, acc, nl, cg);
                if (m < 4) {
                    float4* d = (float4*)(Bs + ((m + 1) & 1) * 8192);
                    d[tid] = pc0; d[tid + 512] = pc1;
                    if (m < 3) {
                        pc0 = Wc4[(m + 2) * 1024 + tid];
                        pc1 = Wc4[(m + 2) * 1024 + tid + 512];
                    }
                    if (m == 0) diff2(rhN, sPh, xb, 1, cg, nl);
                    __syncthreads();
                }
            }
            float cxv[4] = {cx.x, cx.y, cx.z, cx.w};
            float hv[4];
            bool isLast = (layer == 1) && (t == last_t);
#pragma unroll
            for (int j = 0; j < 2; j++) {
                int o = cg * 4 + 2 * j;
                float lo, hi; upk2(acc[j], lo, hi);
                float c0 = tanhfast(lo + cxv[2 * j]);
                float c1 = tanhfast(hi + cxv[2 * j + 1]);
                float u0 = uT[o * 34 + nl], u1 = uT[(o + 1) * 34 + nl];
                float h0 = hT[o * 34 + nl], h1 = hT[(o + 1) * 34 + nl];
                hv[2 * j] = u0 * h0 + (1.f - u0) * c0;
                hv[2 * j + 1] = u1 * h1 + (1.f - u1) * c1;
            }
#pragma unroll
            for (int j = 0; j < 2; j++) {
                int o = cg * 4 + 2 * j;
                hN[ng * 68 + o] = hv[2 * j]; hN[ng * 68 + o + 1] = hv[2 * j + 1];
                hT[o * 34 + nl] = hv[2 * j]; hT[(o + 1) * 34 + nl] = hv[2 * j + 1];
            }
            float4 hq = make_float4(hv[0], hv[1], hv[2], hv[3]);
            st_rem_v4(hN_rem_base + cg * 16, hq);   // cg*4 floats
            if (layer == 0)
                *(float4*)(g_Hseq + ((size_t)t * Bn + b) * 4096 + ng * 64 + cg * 4) = hq;
            if (isLast)
                *(float4*)(g_Last + (size_t)(b * 64 + ng) * 64 + cg * 4) = hq;
        }
        CLUSTER_SYNC();   // h halves exchanged
    }
}

// ---------- output head ----------
__global__ void k_head(const float* __restrict__ fcw, const float* __restrict__ fcb,
                       const float* __restrict__ idw, const float* __restrict__ idb,
                       float* __restrict__ out) {
    __shared__ float hb[4096];
    __shared__ float w[64 * 54];
    __shared__ float bias[54];
    int b = blockIdx.x, tid = threadIdx.x;
    for (int i = tid; i < 4096; i += 256) hb[i] = fmaxf(g_Last[b * 4096 + i], 0.f);
    for (int i = tid; i < 64 * 54; i += 256) {
        int k = i / 54, c = i % 54;
        w[i] = (c < 4) ? fcw[k * 4 + c] : idw[k * 50 + c - 4];
    }
    if (tid < 54) bias[tid] = (tid < 4) ? fcb[tid] : idb[tid - 4];
    __syncthreads();
    if (tid < 54) {
        float best = -INFINITY;
        for (int nn = 0; nn < 64; nn++) {
            float s = bias[tid];
            for (int k = 0; k < 64; k++) s += hb[nn * 64 + k] * w[k * 54 + tid];
            best = fmaxf(best, s);
        }
        if (tid < 4) out[b * 4 + tid] = best;
        else out[256 + b * 50 + tid - 4] = best;
    }
}

extern "C" void kernel_launch(void* const* d_in, const int* in_sizes, int n_in,
                              void* d_out, int out_size) {
    const float* xseq = (const float*)d_in[0];
    const int* seql = (const int*)d_in[1];
    const float* S0 = (const float*)d_in[2];
    const float* S1 = (const float*)d_in[3];
    const float* Wg0 = (const float*)d_in[4]; const float* bg0 = (const float*)d_in[5];
    const float* Wc0 = (const float*)d_in[6]; const float* bc0 = (const float*)d_in[7];
    const float* Wg1 = (const float*)d_in[8]; const float* bg1 = (const float*)d_in[9];
    const float* Wc1 = (const float*)d_in[10]; const float* bc1 = (const float*)d_in[11];
    const float* fcw = (const float*)d_in[12]; const float* fcb = (const float*)d_in[13];
    const float* idw = (const float*)d_in[14]; const float* idb = (const float*)d_in[15];
    float* out = (float*)d_out;

    const int SM_PRE = (4224 + 4352 + 16896 + 12288 + 16384) * 4;   // 216576
    const int SM_REC = (16384 + 4352 + 4352 + 8192 + 2176 + 2176 + 2176 + 8704) * 4; // 194048
    cudaFuncSetAttribute(k_pre, cudaFuncAttributeMaxDynamicSharedMemorySize, SM_PRE);
    cudaFuncSetAttribute(k_recur, cudaFuncAttributeMaxDynamicSharedMemorySize, SM_REC);

    k_prep<<<1, 256>>>(S0, S1);
    k_pack<<<240, 256>>>(Wg0, Wc0, Wg1, Wc1);

    k_pre<<<dim3(Tn, Bn), 512, SM_PRE>>>(0, xseq, bg0, bc0);
    k_recur<<<dim3(2, Bn), 512, SM_REC>>>(0, seql);
    k_pre<<<dim3(Tn, Bn), 512, SM_PRE>>>(1, xseq, bg1, bc1);
    k_recur<<<dim3(2, Bn), 512, SM_REC>>>(1, seql);

    k_head<<<Bn, 256>>>(fcw, fcb, idw, idb, out);
}

// round 9
// speedup vs baseline: 2.2432x; 1.2326x over previous
#include <cuda_runtime.h>
#include <math.h>

typedef unsigned long long ull;
#define Tn 96
#define Bn 64

__device__ __forceinline__ ull pk2(float lo, float hi) {
    ull r; asm("mov.b64 %0,{%1,%2};" : "=l"(r) : "f"(lo), "f"(hi)); return r;
}
__device__ __forceinline__ void upk2(ull v, float &a, float &b) {
    asm("mov.b64 {%0,%1},%2;" : "=f"(a), "=f"(b) : "l"(v));
}
__device__ __forceinline__ void ffma2(ull &d, ull a, ull b) {
    asm("fma.rn.f32x2 %0,%1,%2,%0;" : "+l"(d) : "l"(a), "l"(b));
}
__device__ __forceinline__ float sigm(float x) { return 1.f / (1.f + __expf(-x)); }
__device__ __forceinline__ float tanhfast(float x) {
    float t = __expf(-2.f * fabsf(x));
    return copysignf((1.f - t) / (1.f + t), x);
}
__device__ __forceinline__ unsigned s2u(const void* p) {
    unsigned a;
    asm("{ .reg .u64 t; cvta.to.shared.u64 t, %1; cvt.u32.u64 %0, t; }" : "=r"(a) : "l"(p));
    return a;
}
__device__ __forceinline__ unsigned mapa_rank(unsigned a, unsigned rank) {
    unsigned r; asm("mapa.shared::cluster.u32 %0, %1, %2;" : "=r"(r) : "r"(a), "r"(rank));
    return r;
}
__device__ __forceinline__ void st_rem_v4(unsigned a, float4 v) {
    asm volatile("st.shared::cluster.v4.f32 [%0], {%1,%2,%3,%4};"
                 :: "r"(a), "f"(v.x), "f"(v.y), "f"(v.z), "f"(v.w) : "memory");
}
#define CLUSTER_SYNC() do { \
    asm volatile("barrier.cluster.arrive.aligned;" ::: "memory"); \
    asm volatile("barrier.cluster.wait.aligned;" ::: "memory"); \
} while (0)

// ---------- device-global scratch ----------
__device__ __align__(256) float g_Pt[4 * 4096];                   // [m][k][n] = P_{m+1}[n][k]
__device__ __align__(256) float g_WX[2][5 * 64 * 192];
__device__ __align__(256) float g_WgH[2][5 * 64 * 128];
__device__ __align__(256) float g_WcH[2][5 * 64 * 64];
__device__ __align__(256) float g_Gx[(size_t)Tn * Bn * 64 * 128];
__device__ __align__(256) float g_Cx[(size_t)Tn * Bn * 64 * 64];
__device__ __align__(256) float g_Hseq[(size_t)Tn * Bn * 4096];
__device__ __align__(256) float g_Last[Bn * 4096];

// ---------- P matrices ----------
__global__ void k_prep(const float* __restrict__ S0, const float* __restrict__ S1) {
    __shared__ float s0[4096], s1[4096];
    int tid = threadIdx.x;
    for (int i = tid; i < 4096; i += 256) { s0[i] = S0[i]; s1[i] = S1[i]; }
    __syncthreads();
    for (int i = tid; i < 4096; i += 256) {
        int n = i >> 6, k = i & 63;
        float a2 = 0.f, a3 = 0.f;
        for (int j = 0; j < 64; j++) {
            a2 += s0[n * 64 + j] * s0[j * 64 + k];
            a3 += s1[n * 64 + j] * s0[j * 64 + k];
        }
        g_Pt[k * 64 + n] = s0[i];
        g_Pt[4096 + k * 64 + n] = 2.f * a2 - (n == k ? 1.f : 0.f);
        g_Pt[2 * 4096 + k * 64 + n] = a3;
    }
    __syncthreads();
    for (int i = tid; i < 4096; i += 256) {
        int n = i >> 6, k = i & 63;
        float a4 = 0.f;
        for (int j = 0; j < 64; j++) a4 += s1[n * 64 + j] * g_Pt[2 * 4096 + k * 64 + j];
        g_Pt[3 * 4096 + k * 64 + n] = 2.f * a4 - s0[i];
    }
}

// ---------- weight repack ----------
__global__ void k_pack(const float* __restrict__ Wg0, const float* __restrict__ Wc0,
                       const float* __restrict__ Wg1, const float* __restrict__ Wc1) {
    const int WXsz = 5 * 64 * 192, WgHsz = 5 * 64 * 128, WcHsz = 5 * 64 * 64;
    const int PER_L = WXsz + WgHsz + WcHsz;
    for (int i = blockIdx.x * blockDim.x + threadIdx.x; i < 2 * PER_L; i += gridDim.x * blockDim.x) {
        int L = i / PER_L, r = i % PER_L;
        const float* Wg = L ? Wg1 : Wg0;
        const float* Wc = L ? Wc1 : Wc0;
        if (r < WXsz) {
            int m = r / (64 * 192), k = (r / 192) % 64, o = r % 192;
            g_WX[L][r] = (o < 128) ? Wg[(k * 5 + m) * 128 + o] : Wc[(k * 5 + m) * 64 + (o - 128)];
        } else if (r < WXsz + WgHsz) {
            int q = r - WXsz, m = q / (64 * 128), k = (q / 128) % 64, o = q % 128;
            g_WgH[L][q] = Wg[((64 + k) * 5 + m) * 128 + o];
        } else {
            int q = r - WXsz - WgHsz, m = q / 4096, k = (q / 64) % 64, o = q % 64;
            g_WcH[L][q] = Wc[((64 + k) * 5 + m) * 64 + o];
        }
    }
}

// ================= k_pre: one CTA per (t,b), seql-gated =================
__device__ __forceinline__ void diffpre(const float* __restrict__ xN,
                                        const float* __restrict__ sP,
                                        float* __restrict__ xb,
                                        int pass, int grp, int n64) {
    int m = pass * 2 + (grp >> 2);
    int fg = grp & 3;
    const float* P = sP + m * 4096 + n64;
    const float* s = xN + fg * 16;
    ull d[8] = {0, 0, 0, 0, 0, 0, 0, 0};
#pragma unroll 2
    for (int k = 0; k < 64; k++) {
        float p = P[k * 64];
        ull p2 = pk2(p, p);
        const ulonglong2* hv = (const ulonglong2*)(s + k * 68);
        ulonglong2 a = hv[0], b = hv[1], c = hv[2], e = hv[3];
        ffma2(d[0], p2, a.x); ffma2(d[1], p2, a.y);
        ffma2(d[2], p2, b.x); ffma2(d[3], p2, b.y);
        ffma2(d[4], p2, c.x); ffma2(d[5], p2, c.y);
        ffma2(d[6], p2, e.x); ffma2(d[7], p2, e.y);
    }
    float* dst = xb + m * 4224 + fg * 16 * 66 + n64;
#pragma unroll
    for (int j = 0; j < 8; j++) {
        float x, y; upk2(d[j], x, y);
        dst[(2 * j) * 66] = x;
        dst[(2 * j + 1) * 66] = y;
    }
}

__device__ __forceinline__ void gemm_pre(const float* __restrict__ A,
                                         const float* __restrict__ B,
                                         ull* acc, int nl, int cg) {
#pragma unroll 2
    for (int k = 0; k < 64; k++) {
        float a0 = A[k * 66 + nl];
        float a1 = A[k * 66 + nl + 32];
        ull q0 = pk2(a0, a0), q1 = pk2(a1, a1);
        const ulonglong2* br = (const ulonglong2*)(B + k * 192 + cg * 12);
        ulonglong2 w0 = br[0], w1 = br[1], w2 = br[2];
        ffma2(acc[0], q0, w0.x); ffma2(acc[1], q0, w0.y);
        ffma2(acc[2], q0, w1.x); ffma2(acc[3], q0, w1.y);
        ffma2(acc[4], q0, w2.x); ffma2(acc[5], q0, w2.y);
        ffma2(acc[6], q1, w0.x); ffma2(acc[7], q1, w0.y);
        ffma2(acc[8], q1, w1.x); ffma2(acc[9], q1, w1.y);
        ffma2(acc[10], q1, w2.x); ffma2(acc[11], q1, w2.y);
    }
}

__global__ void __launch_bounds__(512, 1) k_pre(int layer, const float* __restrict__ xin,
                                                const float* __restrict__ bg,
                                                const float* __restrict__ bc,
                                                const int* __restrict__ seql) {
    const int t = blockIdx.x, b = blockIdx.y;
    if (t >= seql[b]) return;   // this (t,b) is never consumed downstream
    extern __shared__ float sm[];
    float* xT = sm;             // [64f][66]
    float* xN = sm + 4224;      // [64n][68]
    float* xb = sm + 8576;      // [4][64f][66]
    float* Bs = sm + 25472;     // [64][192]
    float* sP = sm + 37760;     // [4][64][64]
    const int tid = threadIdx.x;
    const int nl = tid & 31, cg = tid >> 5;
    const int n64 = tid & 63, grp = tid >> 6;

    const float* src = layer ? (g_Hseq + ((size_t)t * Bn + b) * 4096)
                             : (xin + ((size_t)b * Tn + t) * 4096);
    for (int i = tid; i < 1024; i += 512) {
        float4 v = __ldg((const float4*)src + i);
        int n = i >> 4, fo = (i & 15) << 2;
        *(float4*)&xN[n * 68 + fo] = v;
        xT[fo * 66 + n] = v.x; xT[(fo + 1) * 66 + n] = v.y;
        xT[(fo + 2) * 66 + n] = v.z; xT[(fo + 3) * 66 + n] = v.w;
    }
    for (int i = tid * 4; i < 16384; i += 2048)
        *(float4*)&sP[i] = *(const float4*)&g_Pt[i];
    const float4* W4 = (const float4*)g_WX[layer];
    float4 pf[6];
#pragma unroll
    for (int j = 0; j < 6; j++) pf[j] = W4[tid + j * 512];
    __syncthreads();

    ull acc[12] = {0, 0, 0, 0, 0, 0, 0, 0, 0, 0, 0, 0};
#pragma unroll
    for (int m = 0; m < 5; m++) {
#pragma unroll
        for (int j = 0; j < 6; j++) ((float4*)Bs)[tid + j * 512] = pf[j];
        if (m < 4) {
#pragma unroll
            for (int j = 0; j < 6; j++) pf[j] = W4[(m + 1) * 3072 + tid + j * 512];
        }
        if (m == 0) diffpre(xN, sP, xb, 0, grp, n64);
        if (m == 1) diffpre(xN, sP, xb, 1, grp, n64);
        __syncthreads();
        gemm_pre((m == 0) ? xT : (xb + (m - 1) * 4224), Bs, acc, nl, cg);
        __syncthreads();
    }

    size_t gb = ((size_t)t * Bn + b) * 64;
#pragma unroll
    for (int h = 0; h < 2; h++) {
        int n = nl + h * 32;
        float* Gp = g_Gx + (gb + n) * 128;
        float* Cp = g_Cx + (gb + n) * 64;
#pragma unroll
        for (int j = 0; j < 6; j++) {
            int o = cg * 12 + 2 * j;
            float lo, hi; upk2(acc[h * 6 + j], lo, hi);
            if (o < 128) {
                Gp[o] = lo + __ldg(bg + o);
                Gp[o + 1] = hi + __ldg(bg + o + 1);
            } else {
                Cp[o - 128] = lo + __ldg(bc + o - 128);
                Cp[o - 127] = hi + __ldg(bc + o - 127);
            }
        }
    }
}

// ================= recur v6: 2-CTA cluster, single-pass diffusion, seql cap =================
// warp w: m = w>>2, feature group fg = w&3 (16 features). Amortizes P-load over 16 features.
__device__ __forceinline__ void diff1(const float* __restrict__ srcN,
                                      const float* __restrict__ sPh,
                                      float* __restrict__ xb,
                                      int w, int nl) {
    int m = w >> 2;
    int fg = w & 3;
    const float* P = sPh + m * 2048 + nl;
    const float* s = srcN + fg * 16;
    ull d[8] = {0, 0, 0, 0, 0, 0, 0, 0};
#pragma unroll 2
    for (int k = 0; k < 64; k++) {
        float p = P[k * 32];
        ull p2 = pk2(p, p);
        const ulonglong2* hv = (const ulonglong2*)(s + k * 68);
        ulonglong2 a = hv[0], b = hv[1], c = hv[2], e = hv[3];
        ffma2(d[0], p2, a.x); ffma2(d[1], p2, a.y);
        ffma2(d[2], p2, b.x); ffma2(d[3], p2, b.y);
        ffma2(d[4], p2, c.x); ffma2(d[5], p2, c.y);
        ffma2(d[6], p2, e.x); ffma2(d[7], p2, e.y);
    }
    float* dst = xb + m * 2176 + fg * 16 * 34 + nl;
#pragma unroll
    for (int j = 0; j < 8; j++) {
        float x, y; upk2(d[j], x, y);
        dst[(2 * j) * 34] = x;
        dst[(2 * j + 1) * 34] = y;
    }
}

__device__ __forceinline__ void gemm_gate(const float* __restrict__ A,
                                          const float* __restrict__ B,
                                          ull* acc, int nl, int cg) {
#pragma unroll 4
    for (int k = 0; k < 64; k++) {
        float a = A[k * 34 + nl];
        ull a2 = pk2(a, a);
        const ulonglong2* br = (const ulonglong2*)(B + k * 128 + cg * 8);
        ulonglong2 w0 = br[0], w1 = br[1];
        ffma2(acc[0], a2, w0.x); ffma2(acc[1], a2, w0.y);
        ffma2(acc[2], a2, w1.x); ffma2(acc[3], a2, w1.y);
    }
}
__device__ __forceinline__ void gemm_cand(const float* __restrict__ A,
                                          const float* __restrict__ B,
                                          ull* acc, int nl, int cg) {
#pragma unroll 4
    for (int k = 0; k < 64; k++) {
        float a = A[k * 34 + nl];
        ull a2 = pk2(a, a);
        ulonglong2 w = *(const ulonglong2*)(B + k * 64 + cg * 4);
        ffma2(acc[0], a2, w.x); ffma2(acc[1], a2, w.y);
    }
}

__global__ void __launch_bounds__(512, 1) __cluster_dims__(2, 1, 1)
k_recur(int layer, const int* __restrict__ seql) {
    extern __shared__ float sm[];
    float* Bs  = sm;                  // [2][8192]
    float* hN  = sm + 16384;          // [64][68]
    float* rhN = hN + 4352;           // [64][68]
    float* sPh = rhN + 4352;          // [4][64][32]
    float* hT  = sPh + 8192;          // [64f][34]
    float* rhT = hT + 2176;           // [64f][34]
    float* uT  = rhT + 2176;          // [64o][34]
    float* xb  = uT + 2176;           // [4][64f][34]

    const int tid = threadIdx.x;
    const int hf = blockIdx.x & 1;    // cluster rank
    const int b = blockIdx.y;
    const int nl = tid & 31;
    const int cg = tid >> 5;          // warp id 0..15
    const int ng = hf * 32 + nl;
    const unsigned peer_rank = hf ^ 1;

    for (int i = tid; i < 8192; i += 512) {
        int m = i >> 11, r = i & 2047, k = r >> 5, nn = r & 31;
        sPh[i] = g_Pt[m * 4096 + k * 64 + hf * 32 + nn];
    }
    for (int i = tid; i < 64 * 68; i += 512) hN[i] = 0.f;
    for (int i = tid; i < 64 * 34; i += 512) hT[i] = 0.f;
    const unsigned rhN_rem_base = mapa_rank(s2u(&rhN[ng * 68]), peer_rank);
    const unsigned hN_rem_base  = mapa_rank(s2u(&hN[ng * 68]), peer_rank);
    CLUSTER_SYNC();

    const float4* Wg4 = (const float4*)g_WgH[layer];
    const float4* Wc4 = (const float4*)g_WcH[layer];
    const int last_t = seql[b] - 1;

    for (int t = 0; t <= last_t; t++) {
        // ================= GATE =================
        {
            const float* GxP = g_Gx + (((size_t)t * Bn + b) * 64 + ng) * 128 + cg * 8;
            float4 gx0 = __ldg((const float4*)GxP);
            float4 gx1 = __ldg((const float4*)GxP + 1);
            ull acc[4] = {0, 0, 0, 0};
            float4 pf0 = Wg4[tid], pf1 = Wg4[tid + 512], pf2 = Wg4[tid + 1024], pf3 = Wg4[tid + 1536];
            ((float4*)Bs)[tid] = pf0; ((float4*)Bs)[tid + 512] = pf1;
            ((float4*)Bs)[tid + 1024] = pf2; ((float4*)Bs)[tid + 1536] = pf3;
            pf0 = Wg4[2048 + tid]; pf1 = Wg4[2048 + tid + 512];
            pf2 = Wg4[2048 + tid + 1024]; pf3 = Wg4[2048 + tid + 1536];
            diff1(hN, sPh, xb, cg, nl);   // all 4 slices in one pass
            __syncthreads();
#pragma unroll
            for (int m = 0; m < 5; m++) {
                gemm_gate((m == 0) ? hT : (xb + (m - 1) * 2176), Bs + (m & 1) * 8192, acc, nl, cg);
                if (m < 4) {
                    float4* d = (float4*)(Bs + ((m + 1) & 1) * 8192);
                    d[tid] = pf0; d[tid + 512] = pf1; d[tid + 1024] = pf2; d[tid + 1536] = pf3;
                    if (m < 3) {
                        pf0 = Wg4[(m + 2) * 2048 + tid];        pf1 = Wg4[(m + 2) * 2048 + tid + 512];
                        pf2 = Wg4[(m + 2) * 2048 + tid + 1024]; pf3 = Wg4[(m + 2) * 2048 + tid + 1536];
                    }
                    __syncthreads();
                }
            }
            float gx[8] = {gx0.x, gx0.y, gx0.z, gx0.w, gx1.x, gx1.y, gx1.z, gx1.w};
            if (cg < 8) {
                float rv[8];
#pragma unroll
                for (int j = 0; j < 4; j++) {
                    int o = cg * 8 + 2 * j;
                    float lo, hi; upk2(acc[j], lo, hi);
                    float h0 = hT[o * 34 + nl], h1 = hT[(o + 1) * 34 + nl];
                    float r0 = sigm(lo + gx[2 * j]) * h0;
                    float r1 = sigm(hi + gx[2 * j + 1]) * h1;
                    rhN[ng * 68 + o] = r0; rhN[ng * 68 + o + 1] = r1;
                    rhT[o * 34 + nl] = r0; rhT[(o + 1) * 34 + nl] = r1;
                    rv[2 * j] = r0; rv[2 * j + 1] = r1;
                }
                unsigned rem = rhN_rem_base + cg * 32;
                st_rem_v4(rem, make_float4(rv[0], rv[1], rv[2], rv[3]));
                st_rem_v4(rem + 16, make_float4(rv[4], rv[5], rv[6], rv[7]));
            } else {
#pragma unroll
                for (int j = 0; j < 4; j++) {
                    int o = cg * 8 + 2 * j;
                    float lo, hi; upk2(acc[j], lo, hi);
                    uT[(o - 64) * 34 + nl] = sigm(lo + gx[2 * j]);
                    uT[(o - 63) * 34 + nl] = sigm(hi + gx[2 * j + 1]);
                }
            }
        }
        CLUSTER_SYNC();

        // ================= CAND =================
        {
            const float* CxP = g_Cx + (((size_t)t * Bn + b) * 64 + ng) * 64 + cg * 4;
            float4 cx = __ldg((const float4*)CxP);
            ull acc[2] = {0, 0};
            float4 pc0 = Wc4[tid], pc1 = Wc4[tid + 512];
            ((float4*)Bs)[tid] = pc0; ((float4*)Bs)[tid + 512] = pc1;
            pc0 = Wc4[1024 + tid]; pc1 = Wc4[1024 + tid + 512];
            diff1(rhN, sPh, xb, cg, nl);
            __syncthreads();
#pragma unroll
            for (int m = 0; m < 5; m++) {
                gemm_cand((m == 0) ? rhT : (xb + (m - 1) * 2176), Bs + (m & 1) * 8192, acc, nl, cg);
                if (m < 4) {
                    float4* d = (float4*)(Bs + ((m + 1) & 1) * 8192);
                    d[tid] = pc0; d[tid + 512] = pc1;
                    if (m < 3) {
                        pc0 = Wc4[(m + 2) * 1024 + tid];
                        pc1 = Wc4[(m + 2) * 1024 + tid + 512];
                    }
                    __syncthreads();
                }
            }
            float cxv[4] = {cx.x, cx.y, cx.z, cx.w};
            float hv[4];
            bool isLast = (layer == 1) && (t == last_t);
#pragma unroll
            for (int j = 0; j < 2; j++) {
                int o = cg * 4 + 2 * j;
                float lo, hi; upk2(acc[j], lo, hi);
                float c0 = tanhfast(lo + cxv[2 * j]);
                float c1 = tanhfast(hi + cxv[2 * j + 1]);
                float u0 = uT[o * 34 + nl], u1 = uT[(o + 1) * 34 + nl];
                float h0 = hT[o * 34 + nl], h1 = hT[(o + 1) * 34 + nl];
                hv[2 * j] = u0 * h0 + (1.f - u0) * c0;
                hv[2 * j + 1] = u1 * h1 + (1.f - u1) * c1;
            }
#pragma unroll
            for (int j = 0; j < 2; j++) {
                int o = cg * 4 + 2 * j;
                hN[ng * 68 + o] = hv[2 * j]; hN[ng * 68 + o + 1] = hv[2 * j + 1];
                hT[o * 34 + nl] = hv[2 * j]; hT[(o + 1) * 34 + nl] = hv[2 * j + 1];
            }
            float4 hq = make_float4(hv[0], hv[1], hv[2], hv[3]);
            st_rem_v4(hN_rem_base + cg * 16, hq);
            if (layer == 0)
                *(float4*)(g_Hseq + ((size_t)t * Bn + b) * 4096 + ng * 64 + cg * 4) = hq;
            if (isLast)
                *(float4*)(g_Last + (size_t)(b * 64 + ng) * 64 + cg * 4) = hq;
        }
        CLUSTER_SYNC();
    }
}

// ---------- output head ----------
__global__ void k_head(const float* __restrict__ fcw, const float* __restrict__ fcb,
                       const float* __restrict__ idw, const float* __restrict__ idb,
                       float* __restrict__ out) {
    __shared__ float hb[4096];
    __shared__ float w[64 * 54];
    __shared__ float bias[54];
    int b = blockIdx.x, tid = threadIdx.x;
    for (int i = tid; i < 4096; i += 256) hb[i] = fmaxf(g_Last[b * 4096 + i], 0.f);
    for (int i = tid; i < 64 * 54; i += 256) {
        int k = i / 54, c = i % 54;
        w[i] = (c < 4) ? fcw[k * 4 + c] : idw[k * 50 + c - 4];
    }
    if (tid < 54) bias[tid] = (tid < 4) ? fcb[tid] : idb[tid - 4];
    __syncthreads();
    if (tid < 54) {
        float best = -INFINITY;
        for (int nn = 0; nn < 64; nn++) {
            float s = bias[tid];
            for (int k = 0; k < 64; k++) s += hb[nn * 64 + k] * w[k * 54 + tid];
            best = fmaxf(best, s);
        }
        if (tid < 4) out[b * 4 + tid] = best;
        else out[256 + b * 50 + tid - 4] = best;
    }
}

extern "C" void kernel_launch(void* const* d_in, const int* in_sizes, int n_in,
                              void* d_out, int out_size) {
    const float* xseq = (const float*)d_in[0];
    const int* seql = (const int*)d_in[1];
    const float* S0 = (const float*)d_in[2];
    const float* S1 = (const float*)d_in[3];
    const float* Wg0 = (const float*)d_in[4]; const float* bg0 = (const float*)d_in[5];
    const float* Wc0 = (const float*)d_in[6]; const float* bc0 = (const float*)d_in[7];
    const float* Wg1 = (const float*)d_in[8]; const float* bg1 = (const float*)d_in[9];
    const float* Wc1 = (const float*)d_in[10]; const float* bc1 = (const float*)d_in[11];
    const float* fcw = (const float*)d_in[12]; const float* fcb = (const float*)d_in[13];
    const float* idw = (const float*)d_in[14]; const float* idb = (const float*)d_in[15];
    float* out = (float*)d_out;

    const int SM_PRE = (4224 + 4352 + 16896 + 12288 + 16384) * 4;   // 216576
    const int SM_REC = (16384 + 4352 + 4352 + 8192 + 2176 + 2176 + 2176 + 8704) * 4; // 194048
    cudaFuncSetAttribute(k_pre, cudaFuncAttributeMaxDynamicSharedMemorySize, SM_PRE);
    cudaFuncSetAttribute(k_recur, cudaFuncAttributeMaxDynamicSharedMemorySize, SM_REC);

    k_prep<<<1, 256>>>(S0, S1);
    k_pack<<<240, 256>>>(Wg0, Wc0, Wg1, Wc1);

    k_pre<<<dim3(Tn, Bn), 512, SM_PRE>>>(0, xseq, bg0, bc0, seql);
    k_recur<<<dim3(2, Bn), 512, SM_REC>>>(0, seql);
    k_pre<<<dim3(Tn, Bn), 512, SM_PRE>>>(1, xseq, bg1, bc1, seql);
    k_recur<<<dim3(2, Bn), 512, SM_REC>>>(1, seql);

    k_head<<<Bn, 256>>>(fcw, fcb, idw, idb, out);
}

// round 10
// speedup vs baseline: 2.5345x; 1.1298x over previous
#include <cuda_runtime.h>
#include <math.h>

typedef unsigned long long ull;
#define Tn 96
#define Bn 64

__device__ __forceinline__ ull pk2(float lo, float hi) {
    ull r; asm("mov.b64 %0,{%1,%2};" : "=l"(r) : "f"(lo), "f"(hi)); return r;
}
__device__ __forceinline__ void upk2(ull v, float &a, float &b) {
    asm("mov.b64 {%0,%1},%2;" : "=f"(a), "=f"(b) : "l"(v));
}
__device__ __forceinline__ void ffma2(ull &d, ull a, ull b) {
    asm("fma.rn.f32x2 %0,%1,%2,%0;" : "+l"(d) : "l"(a), "l"(b));
}
__device__ __forceinline__ float sigm(float x) { return 1.f / (1.f + __expf(-x)); }
__device__ __forceinline__ float tanhfast(float x) {
    float t = __expf(-2.f * fabsf(x));
    return copysignf((1.f - t) / (1.f + t), x);
}
__device__ __forceinline__ unsigned s2u(const void* p) {
    unsigned a;
    asm("{ .reg .u64 t; cvta.to.shared.u64 t, %1; cvt.u32.u64 %0, t; }" : "=r"(a) : "l"(p));
    return a;
}
__device__ __forceinline__ unsigned mapa_rank(unsigned a, unsigned rank) {
    unsigned r; asm("mapa.shared::cluster.u32 %0, %1, %2;" : "=r"(r) : "r"(a), "r"(rank));
    return r;
}
__device__ __forceinline__ void st_rem_v4(unsigned a, float4 v) {
    asm volatile("st.shared::cluster.v4.f32 [%0], {%1,%2,%3,%4};"
                 :: "r"(a), "f"(v.x), "f"(v.y), "f"(v.z), "f"(v.w) : "memory");
}
__device__ __forceinline__ void flag_release(int* p) {
    asm volatile("red.release.gpu.global.add.s32 [%0], 1;" :: "l"(p) : "memory");
}
__device__ __forceinline__ int flag_acq(const int* p) {
    int v; asm volatile("ld.acquire.gpu.global.s32 %0, [%1];" : "=r"(v) : "l"(p) : "memory");
    return v;
}
#define CLUSTER_SYNC() do { \
    asm volatile("barrier.cluster.arrive.aligned;" ::: "memory"); \
    asm volatile("barrier.cluster.wait.aligned;" ::: "memory"); \
} while (0)

// ---------- device-global scratch ----------
__device__ __align__(256) float g_Pt[4 * 4096];                   // [m][k][n] = P_{m+1}[n][k]
__device__ __align__(256) float g_WX[2][5 * 64 * 192];
__device__ __align__(256) float g_WgH[2][5 * 64 * 128];
__device__ __align__(256) float g_WcH[2][5 * 64 * 64];
__device__ __align__(256) float g_Gx[(size_t)Tn * Bn * 64 * 128];
__device__ __align__(256) float g_Cx[(size_t)Tn * Bn * 64 * 64];
__device__ __align__(256) float g_Hseq[(size_t)Tn * Bn * 4096];
__device__ __align__(256) float g_Last[Bn * 4096];
__device__ __align__(256) int   g_prog[128];                      // [b][hf] layer-0 step progress

// ---------- P matrices ----------
__global__ void k_prep(const float* __restrict__ S0, const float* __restrict__ S1) {
    __shared__ float s0[4096], s1[4096];
    int tid = threadIdx.x;
    if (tid < 128) g_prog[tid] = 0;      // reset progress flags each replay
    for (int i = tid; i < 4096; i += 256) { s0[i] = S0[i]; s1[i] = S1[i]; }
    __syncthreads();
    for (int i = tid; i < 4096; i += 256) {
        int n = i >> 6, k = i & 63;
        float a2 = 0.f, a3 = 0.f;
        for (int j = 0; j < 64; j++) {
            a2 += s0[n * 64 + j] * s0[j * 64 + k];
            a3 += s1[n * 64 + j] * s0[j * 64 + k];
        }
        g_Pt[k * 64 + n] = s0[i];
        g_Pt[4096 + k * 64 + n] = 2.f * a2 - (n == k ? 1.f : 0.f);
        g_Pt[2 * 4096 + k * 64 + n] = a3;
    }
    __syncthreads();
    for (int i = tid; i < 4096; i += 256) {
        int n = i >> 6, k = i & 63;
        float a4 = 0.f;
        for (int j = 0; j < 64; j++) a4 += s1[n * 64 + j] * g_Pt[2 * 4096 + k * 64 + j];
        g_Pt[3 * 4096 + k * 64 + n] = 2.f * a4 - s0[i];
    }
}

// ---------- weight repack ----------
__global__ void k_pack(const float* __restrict__ Wg0, const float* __restrict__ Wc0,
                       const float* __restrict__ Wg1, const float* __restrict__ Wc1) {
    const int WXsz = 5 * 64 * 192, WgHsz = 5 * 64 * 128, WcHsz = 5 * 64 * 64;
    const int PER_L = WXsz + WgHsz + WcHsz;
    for (int i = blockIdx.x * blockDim.x + threadIdx.x; i < 2 * PER_L; i += gridDim.x * blockDim.x) {
        int L = i / PER_L, r = i % PER_L;
        const float* Wg = L ? Wg1 : Wg0;
        const float* Wc = L ? Wc1 : Wc0;
        if (r < WXsz) {
            int m = r / (64 * 192), k = (r / 192) % 64, o = r % 192;
            g_WX[L][r] = (o < 128) ? Wg[(k * 5 + m) * 128 + o] : Wc[(k * 5 + m) * 64 + (o - 128)];
        } else if (r < WXsz + WgHsz) {
            int q = r - WXsz, m = q / (64 * 128), k = (q / 128) % 64, o = q % 128;
            g_WgH[L][q] = Wg[((64 + k) * 5 + m) * 128 + o];
        } else {
            int q = r - WXsz - WgHsz, m = q / 4096, k = (q / 64) % 64, o = q % 64;
            g_WcH[L][q] = Wc[((64 + k) * 5 + m) * 64 + o];
        }
    }
}

// ================= pre body (proven layout, shared by standalone + fused) =================
__device__ __forceinline__ void diffpre(const float* __restrict__ xN,
                                        const float* __restrict__ sP,
                                        float* __restrict__ xb,
                                        int pass, int grp, int n64) {
    int m = pass * 2 + (grp >> 2);
    int fg = grp & 3;
    const float* P = sP + m * 4096 + n64;
    const float* s = xN + fg * 16;
    ull d[8] = {0, 0, 0, 0, 0, 0, 0, 0};
#pragma unroll 2
    for (int k = 0; k < 64; k++) {
        float p = P[k * 64];
        ull p2 = pk2(p, p);
        const ulonglong2* hv = (const ulonglong2*)(s + k * 68);
        ulonglong2 a = hv[0], b = hv[1], c = hv[2], e = hv[3];
        ffma2(d[0], p2, a.x); ffma2(d[1], p2, a.y);
        ffma2(d[2], p2, b.x); ffma2(d[3], p2, b.y);
        ffma2(d[4], p2, c.x); ffma2(d[5], p2, c.y);
        ffma2(d[6], p2, e.x); ffma2(d[7], p2, e.y);
    }
    float* dst = xb + m * 4224 + fg * 16 * 66 + n64;
#pragma unroll
    for (int j = 0; j < 8; j++) {
        float x, y; upk2(d[j], x, y);
        dst[(2 * j) * 66] = x;
        dst[(2 * j + 1) * 66] = y;
    }
}

__device__ __forceinline__ void gemm_pre(const float* __restrict__ A,
                                         const float* __restrict__ B,
                                         ull* acc, int nl, int cg) {
#pragma unroll 2
    for (int k = 0; k < 64; k++) {
        float a0 = A[k * 66 + nl];
        float a1 = A[k * 66 + nl + 32];
        ull q0 = pk2(a0, a0), q1 = pk2(a1, a1);
        const ulonglong2* br = (const ulonglong2*)(B + k * 192 + cg * 12);
        ulonglong2 w0 = br[0], w1 = br[1], w2 = br[2];
        ffma2(acc[0], q0, w0.x); ffma2(acc[1], q0, w0.y);
        ffma2(acc[2], q0, w1.x); ffma2(acc[3], q0, w1.y);
        ffma2(acc[4], q0, w2.x); ffma2(acc[5], q0, w2.y);
        ffma2(acc[6], q1, w0.x); ffma2(acc[7], q1, w0.y);
        ffma2(acc[8], q1, w1.x); ffma2(acc[9], q1, w1.y);
        ffma2(acc[10], q1, w2.x); ffma2(acc[11], q1, w2.y);
    }
}

__device__ void pre_body(int layer, int t, int b, const float* __restrict__ xin,
                         const float* __restrict__ bg, const float* __restrict__ bc) {
    extern __shared__ float sm[];
    float* xT = sm;             // [64f][66]
    float* xN = sm + 4224;      // [64n][68]
    float* xb = sm + 8576;      // [4][64f][66]
    float* Bs = sm + 25472;     // [64][192]
    float* sP = sm + 37760;     // [4][64][64]
    const int tid = threadIdx.x;
    const int nl = tid & 31, cg = tid >> 5;
    const int n64 = tid & 63, grp = tid >> 6;

    const float* src = layer ? (g_Hseq + ((size_t)t * Bn + b) * 4096)
                             : (xin + ((size_t)b * Tn + t) * 4096);
    for (int i = tid; i < 1024; i += 512) {
        float4 v = __ldg((const float4*)src + i);
        int n = i >> 4, fo = (i & 15) << 2;
        *(float4*)&xN[n * 68 + fo] = v;
        xT[fo * 66 + n] = v.x; xT[(fo + 1) * 66 + n] = v.y;
        xT[(fo + 2) * 66 + n] = v.z; xT[(fo + 3) * 66 + n] = v.w;
    }
    for (int i = tid * 4; i < 16384; i += 2048)
        *(float4*)&sP[i] = *(const float4*)&g_Pt[i];
    const float4* W4 = (const float4*)g_WX[layer];
    float4 pf[6];
#pragma unroll
    for (int j = 0; j < 6; j++) pf[j] = W4[tid + j * 512];
    __syncthreads();

    ull acc[12] = {0, 0, 0, 0, 0, 0, 0, 0, 0, 0, 0, 0};
#pragma unroll
    for (int m = 0; m < 5; m++) {
#pragma unroll
        for (int j = 0; j < 6; j++) ((float4*)Bs)[tid + j * 512] = pf[j];
        if (m < 4) {
#pragma unroll
            for (int j = 0; j < 6; j++) pf[j] = W4[(m + 1) * 3072 + tid + j * 512];
        }
        if (m == 0) diffpre(xN, sP, xb, 0, grp, n64);
        if (m == 1) diffpre(xN, sP, xb, 1, grp, n64);
        __syncthreads();
        gemm_pre((m == 0) ? xT : (xb + (m - 1) * 4224), Bs, acc, nl, cg);
        __syncthreads();
    }

    size_t gb = ((size_t)t * Bn + b) * 64;
#pragma unroll
    for (int h = 0; h < 2; h++) {
        int n = nl + h * 32;
        float* Gp = g_Gx + (gb + n) * 128;
        float* Cp = g_Cx + (gb + n) * 64;
#pragma unroll
        for (int j = 0; j < 6; j++) {
            int o = cg * 12 + 2 * j;
            float lo, hi; upk2(acc[h * 6 + j], lo, hi);
            if (o < 128) {
                Gp[o] = lo + __ldg(bg + o);
                Gp[o + 1] = hi + __ldg(bg + o + 1);
            } else {
                Cp[o - 128] = lo + __ldg(bc + o - 128);
                Cp[o - 127] = hi + __ldg(bc + o - 127);
            }
        }
    }
}

// ================= recur v7: node-major A, float4 k-batched loads =================
// smem (floats): Bs 0..16384 | hN 16384 | rhN 20736 | sPhT 25088 | uT 33792 | xbN 35968 | end 44672
__device__ __forceinline__ void diff1(const float* __restrict__ srcN,
                                      const float* __restrict__ sPhT,
                                      float* __restrict__ xbN, int w, int nl) {
    const int m = w >> 2, fg = w & 3;
    const float* P = sPhT + m * 2176 + nl * 68;
    const float* s = srcN + fg * 16;
    ull d[8] = {0, 0, 0, 0, 0, 0, 0, 0};
#pragma unroll 4
    for (int k0 = 0; k0 < 64; k0 += 4) {
        float4 p4 = *(const float4*)(P + k0);
        float pq[4] = {p4.x, p4.y, p4.z, p4.w};
        const float* sk = s + k0 * 68;
#pragma unroll
        for (int q = 0; q < 4; q++) {
            ull p2 = pk2(pq[q], pq[q]);
            const ulonglong2* hv = (const ulonglong2*)(sk + q * 68);
            ulonglong2 a = hv[0], bb = hv[1], c = hv[2], e = hv[3];
            ffma2(d[0], p2, a.x);  ffma2(d[1], p2, a.y);
            ffma2(d[2], p2, bb.x); ffma2(d[3], p2, bb.y);
            ffma2(d[4], p2, c.x);  ffma2(d[5], p2, c.y);
            ffma2(d[6], p2, e.x);  ffma2(d[7], p2, e.y);
        }
    }
    ulonglong2* dst = (ulonglong2*)(xbN + m * 2176 + nl * 68 + fg * 16);
    ulonglong2 v0, v1, v2, v3;
    v0.x = d[0]; v0.y = d[1]; v1.x = d[2]; v1.y = d[3];
    v2.x = d[4]; v2.y = d[5]; v3.x = d[6]; v3.y = d[7];
    dst[0] = v0; dst[1] = v1; dst[2] = v2; dst[3] = v3;
}

__device__ __forceinline__ void gemm_gate(const float* __restrict__ A,
                                          const float* __restrict__ B,
                                          ull* acc, int cg) {
#pragma unroll 4
    for (int k0 = 0; k0 < 64; k0 += 4) {
        float4 a4 = *(const float4*)(A + k0);
        float aq[4] = {a4.x, a4.y, a4.z, a4.w};
#pragma unroll
        for (int q = 0; q < 4; q++) {
            ull a2 = pk2(aq[q], aq[q]);
            const ulonglong2* br = (const ulonglong2*)(B + (k0 + q) * 128 + cg * 8);
            ulonglong2 w0 = br[0], w1 = br[1];
            ffma2(acc[0], a2, w0.x); ffma2(acc[1], a2, w0.y);
            ffma2(acc[2], a2, w1.x); ffma2(acc[3], a2, w1.y);
        }
    }
}
__device__ __forceinline__ void gemm_cand(const float* __restrict__ A,
                                          const float* __restrict__ B,
                                          ull* acc, int cg) {
#pragma unroll 4
    for (int k0 = 0; k0 < 64; k0 += 4) {
        float4 a4 = *(const float4*)(A + k0);
        float aq[4] = {a4.x, a4.y, a4.z, a4.w};
#pragma unroll
        for (int q = 0; q < 4; q++) {
            ull a2 = pk2(aq[q], aq[q]);
            ulonglong2 w = *(const ulonglong2*)(B + (k0 + q) * 64 + cg * 4);
            ffma2(acc[0], a2, w.x); ffma2(acc[1], a2, w.y);
        }
    }
}

template <int LAYER, bool PUBLISH>
__device__ void recur_body(const int* __restrict__ seql) {
    extern __shared__ float sm[];
    float* Bs   = sm;             // [2][8192]
    float* hN   = sm + 16384;     // [64][68]
    float* rhN  = sm + 20736;     // [64][68]
    float* sPhT = sm + 25088;     // [4][32n][68k]
    float* uT   = sm + 33792;     // [64o][34]
    float* xbN  = sm + 35968;     // [4][32n][68f]

    const int tid = threadIdx.x;
    const int hf = blockIdx.x & 1;
    const int b = blockIdx.y;
    const int nl = tid & 31;
    const int cg = tid >> 5;
    const int ng = hf * 32 + nl;
    const unsigned peer_rank = hf ^ 1;

    for (int i = tid; i < 8704; i += 512) {
        int m = i / 2176, r = i % 2176, n = r / 68, k = r % 68;
        sPhT[i] = (k < 64) ? g_Pt[m * 4096 + k * 64 + hf * 32 + n] : 0.f;
    }
    for (int i = tid; i < 4352; i += 512) hN[i] = 0.f;
    const unsigned rhN_rem = mapa_rank(s2u(&rhN[ng * 68]), peer_rank);
    const unsigned hN_rem  = mapa_rank(s2u(&hN[ng * 68]),  peer_rank);
    CLUSTER_SYNC();

    const float4* Wg4 = (const float4*)g_WgH[LAYER];
    const float4* Wc4 = (const float4*)g_WcH[LAYER];
    const int last_t = seql[b] - 1;

    for (int t = 0; t <= last_t; t++) {
        // ================= GATE =================
        {
            const float* GxP = g_Gx + (((size_t)t * Bn + b) * 64 + ng) * 128 + cg * 8;
            float4 gx0 = __ldg((const float4*)GxP);
            float4 gx1 = __ldg((const float4*)GxP + 1);
            ull acc[4] = {0, 0, 0, 0};
            float4 pf0 = Wg4[tid], pf1 = Wg4[tid + 512], pf2 = Wg4[tid + 1024], pf3 = Wg4[tid + 1536];
            ((float4*)Bs)[tid] = pf0; ((float4*)Bs)[tid + 512] = pf1;
            ((float4*)Bs)[tid + 1024] = pf2; ((float4*)Bs)[tid + 1536] = pf3;
            pf0 = Wg4[2048 + tid]; pf1 = Wg4[2048 + tid + 512];
            pf2 = Wg4[2048 + tid + 1024]; pf3 = Wg4[2048 + tid + 1536];
            diff1(hN, sPhT, xbN, cg, nl);
            __syncthreads();
#pragma unroll
            for (int m = 0; m < 5; m++) {
                const float* A = (m == 0) ? (hN + ng * 68) : (xbN + (m - 1) * 2176 + nl * 68);
                gemm_gate(A, Bs + (m & 1) * 8192, acc, cg);
                if (m < 4) {
                    float4* d = (float4*)(Bs + ((m + 1) & 1) * 8192);
                    d[tid] = pf0; d[tid + 512] = pf1; d[tid + 1024] = pf2; d[tid + 1536] = pf3;
                    if (m < 3) {
                        pf0 = Wg4[(m + 2) * 2048 + tid];        pf1 = Wg4[(m + 2) * 2048 + tid + 512];
                        pf2 = Wg4[(m + 2) * 2048 + tid + 1024]; pf3 = Wg4[(m + 2) * 2048 + tid + 1536];
                    }
                    __syncthreads();
                }
            }
            float gx[8] = {gx0.x, gx0.y, gx0.z, gx0.w, gx1.x, gx1.y, gx1.z, gx1.w};
            if (cg < 8) {
                float rv[8];
#pragma unroll
                for (int j = 0; j < 4; j++) {
                    int o = cg * 8 + 2 * j;
                    float lo, hi; upk2(acc[j], lo, hi);
                    float h0 = hN[ng * 68 + o], h1 = hN[ng * 68 + o + 1];
                    float r0 = sigm(lo + gx[2 * j]) * h0;
                    float r1 = sigm(hi + gx[2 * j + 1]) * h1;
                    rhN[ng * 68 + o] = r0; rhN[ng * 68 + o + 1] = r1;
                    rv[2 * j] = r0; rv[2 * j + 1] = r1;
                }
                st_rem_v4(rhN_rem + cg * 32, make_float4(rv[0], rv[1], rv[2], rv[3]));
                st_rem_v4(rhN_rem + cg * 32 + 16, make_float4(rv[4], rv[5], rv[6], rv[7]));
            } else {
#pragma unroll
                for (int j = 0; j < 4; j++) {
                    int o = cg * 8 + 2 * j;
                    float lo, hi; upk2(acc[j], lo, hi);
                    uT[(o - 64) * 34 + nl] = sigm(lo + gx[2 * j]);
                    uT[(o - 63) * 34 + nl] = sigm(hi + gx[2 * j + 1]);
                }
            }
        }
        CLUSTER_SYNC();

        // ================= CAND =================
        {
            const float* CxP = g_Cx + (((size_t)t * Bn + b) * 64 + ng) * 64 + cg * 4;
            float4 cx = __ldg((const float4*)CxP);
            ull acc[2] = {0, 0};
            float4 pc0 = Wc4[tid], pc1 = Wc4[tid + 512];
            ((float4*)Bs)[tid] = pc0; ((float4*)Bs)[tid + 512] = pc1;
            pc0 = Wc4[1024 + tid]; pc1 = Wc4[1024 + tid + 512];
            diff1(rhN, sPhT, xbN, cg, nl);
            __syncthreads();
#pragma unroll
            for (int m = 0; m < 5; m++) {
                const float* A = (m == 0) ? (rhN + ng * 68) : (xbN + (m - 1) * 2176 + nl * 68);
                gemm_cand(A, Bs + (m & 1) * 8192, acc, cg);
                if (m < 4) {
                    float4* d = (float4*)(Bs + ((m + 1) & 1) * 8192);
                    d[tid] = pc0; d[tid + 512] = pc1;
                    if (m < 3) {
                        pc0 = Wc4[(m + 2) * 1024 + tid];
                        pc1 = Wc4[(m + 2) * 1024 + tid + 512];
                    }
                    __syncthreads();
                }
            }
            float cxv[4] = {cx.x, cx.y, cx.z, cx.w};
            float hv[4];
            bool isLast = (LAYER == 1) && (t == last_t);
#pragma unroll
            for (int j = 0; j < 2; j++) {
                int o = cg * 4 + 2 * j;
                float lo, hi; upk2(acc[j], lo, hi);
                float c0 = tanhfast(lo + cxv[2 * j]);
                float c1 = tanhfast(hi + cxv[2 * j + 1]);
                float u0 = uT[o * 34 + nl], u1 = uT[(o + 1) * 34 + nl];
                float h0 = hN[ng * 68 + o], h1 = hN[ng * 68 + o + 1];
                hv[2 * j] = u0 * h0 + (1.f - u0) * c0;
                hv[2 * j + 1] = u1 * h1 + (1.f - u1) * c1;
            }
#pragma unroll
            for (int j = 0; j < 2; j++) {
                int o = cg * 4 + 2 * j;
                hN[ng * 68 + o] = hv[2 * j]; hN[ng * 68 + o + 1] = hv[2 * j + 1];
            }
            float4 hq = make_float4(hv[0], hv[1], hv[2], hv[3]);
            st_rem_v4(hN_rem + cg * 16, hq);
            if (LAYER == 0)
                *(float4*)(g_Hseq + ((size_t)t * Bn + b) * 4096 + ng * 64 + cg * 4) = hq;
            if (isLast)
                *(float4*)(g_Last + (size_t)(b * 64 + ng) * 64 + cg * 4) = hq;
        }
        CLUSTER_SYNC();
        if (PUBLISH && tid == 0) flag_release(&g_prog[b * 2 + hf]);
    }
}

// ---------- standalone layer-0 pre ----------
__global__ void __launch_bounds__(512, 1) k_pre0(const float* __restrict__ xin,
                                                 const float* __restrict__ bg,
                                                 const float* __restrict__ bc,
                                                 const int* __restrict__ seql) {
    int t = blockIdx.x, b = blockIdx.y;
    if (t >= seql[b]) return;
    pre_body(0, t, b, xin, bg, bc);
}

// ---------- fused: layer-0 recurrence + layer-1 x-precompute (flag-gated) ----------
__global__ void __launch_bounds__(512, 1) __cluster_dims__(2, 1, 1)
k_fused(const float* __restrict__ bg1, const float* __restrict__ bc1,
        const int* __restrict__ seql) {
    if (blockIdx.y < Bn) {
        recur_body<0, true>(seql);
    } else {
        int p = (blockIdx.y - Bn) * 2 + blockIdx.x;   // 0..6143, t slow-varying
        int t = p / Bn, b = p % Bn;
        if (t >= seql[b]) return;
        if (threadIdx.x == 0) {
            const int* p0 = &g_prog[b * 2];
            const int* p1 = &g_prog[b * 2 + 1];
            while (flag_acq(p0) <= t) __nanosleep(256);
            while (flag_acq(p1) <= t) __nanosleep(256);
        }
        __syncthreads();
        pre_body(1, t, b, nullptr, bg1, bc1);
    }
}

// ---------- standalone layer-1 recurrence ----------
__global__ void __launch_bounds__(512, 1) __cluster_dims__(2, 1, 1)
k_recur1(const int* __restrict__ seql) {
    recur_body<1, false>(seql);
}

// ---------- output head ----------
__global__ void k_head(const float* __restrict__ fcw, const float* __restrict__ fcb,
                       const float* __restrict__ idw, const float* __restrict__ idb,
                       float* __restrict__ out) {
    __shared__ float hb[4096];
    __shared__ float w[64 * 54];
    __shared__ float bias[54];
    int b = blockIdx.x, tid = threadIdx.x;
    for (int i = tid; i < 4096; i += 256) hb[i] = fmaxf(g_Last[b * 4096 + i], 0.f);
    for (int i = tid; i < 64 * 54; i += 256) {
        int k = i / 54, c = i % 54;
        w[i] = (c < 4) ? fcw[k * 4 + c] : idw[k * 50 + c - 4];
    }
    if (tid < 54) bias[tid] = (tid < 4) ? fcb[tid] : idb[tid - 4];
    __syncthreads();
    if (tid < 54) {
        float best = -INFINITY;
        for (int nn = 0; nn < 64; nn++) {
            float s = bias[tid];
            for (int k = 0; k < 64; k++) s += hb[nn * 64 + k] * w[k * 54 + tid];
            best = fmaxf(best, s);
        }
        if (tid < 4) out[b * 4 + tid] = best;
        else out[256 + b * 50 + tid - 4] = best;
    }
}

extern "C" void kernel_launch(void* const* d_in, const int* in_sizes, int n_in,
                              void* d_out, int out_size) {
    const float* xseq = (const float*)d_in[0];
    const int* seql = (const int*)d_in[1];
    const float* S0 = (const float*)d_in[2];
    const float* S1 = (const float*)d_in[3];
    const float* Wg0 = (const float*)d_in[4]; const float* bg0 = (const float*)d_in[5];
    const float* Wc0 = (const float*)d_in[6]; const float* bc0 = (const float*)d_in[7];
    const float* Wg1 = (const float*)d_in[8]; const float* bg1 = (const float*)d_in[9];
    const float* Wc1 = (const float*)d_in[10]; const float* bc1 = (const float*)d_in[11];
    const float* fcw = (const float*)d_in[12]; const float* fcb = (const float*)d_in[13];
    const float* idw = (const float*)d_in[14]; const float* idb = (const float*)d_in[15];
    float* out = (float*)d_out;

    const int SM_PRE = (4224 + 4352 + 16896 + 12288 + 16384) * 4;   // 216576
    const int SM_REC = 44672 * 4;                                   // 178688
    cudaFuncSetAttribute(k_pre0, cudaFuncAttributeMaxDynamicSharedMemorySize, SM_PRE);
    cudaFuncSetAttribute(k_fused, cudaFuncAttributeMaxDynamicSharedMemorySize, SM_PRE);
    cudaFuncSetAttribute(k_recur1, cudaFuncAttributeMaxDynamicSharedMemorySize, SM_REC);

    k_prep<<<1, 256>>>(S0, S1);
    k_pack<<<240, 256>>>(Wg0, Wc0, Wg1, Wc1);

    k_pre0<<<dim3(Tn, Bn), 512, SM_PRE>>>(xseq, bg0, bc0, seql);
    k_fused<<<dim3(2, Bn + (Tn * Bn) / 2), 512, SM_PRE>>>(bg1, bc1, seql);
    k_recur1<<<dim3(2, Bn), 512, SM_REC>>>(seql);

    k_head<<<Bn, 256>>>(fcw, fcb, idw, idb, out);
}